// round 1
// baseline (speedup 1.0000x reference)
#include <cuda_runtime.h>

#define S_LEN   4096
#define D_MODEL 1024
#define N_HEADS 16
#define HD      64
#define SCALE   0.125f   // 1/sqrt(64)

// Scratch (device globals: allocation-free)
__device__ float g_Q [S_LEN * D_MODEL];
__device__ float g_K [S_LEN * D_MODEL];
__device__ float g_V [S_LEN * D_MODEL];
__device__ float g_Ob[S_LEN * D_MODEL];

// ---------------------------------------------------------------------------
// C[M,N] = A[M,K] @ B[N,K]^T   (both row-major; torch Linear y = x @ W^T)
// 128x128 tile, BK=8, 256 threads, 8x8 micro-tile split into 4x(4x4) quads.
// ---------------------------------------------------------------------------
__global__ __launch_bounds__(256) void sgemm_nt(
    const float* __restrict__ A, const float* __restrict__ B,
    float* __restrict__ C, int M, int N, int K)
{
    __shared__ float As[8][128];
    __shared__ float Bs[8][128];

    const int m0 = blockIdx.y * 128;
    const int n0 = blockIdx.x * 128;
    const int tid = threadIdx.x;

    // tile load mapping: each thread loads one float4 of A and one of B
    const int lr = tid >> 1;          // 0..127 (row within tile)
    const int lk = (tid & 1) * 4;     // 0 or 4 (k offset)
    const float* Ap = A + (size_t)(m0 + lr) * K + lk;
    const float* Bp = B + (size_t)(n0 + lr) * K + lk;

    const int ty = tid >> 4;          // 0..15
    const int tx = tid & 15;          // 0..15

    float acc[8][8];
    #pragma unroll
    for (int i = 0; i < 8; i++)
        #pragma unroll
        for (int j = 0; j < 8; j++) acc[i][j] = 0.f;

    for (int k0 = 0; k0 < K; k0 += 8) {
        float4 a4 = *(const float4*)(Ap + k0);
        float4 b4 = *(const float4*)(Bp + k0);
        __syncthreads();
        As[lk+0][lr] = a4.x; As[lk+1][lr] = a4.y;
        As[lk+2][lr] = a4.z; As[lk+3][lr] = a4.w;
        Bs[lk+0][lr] = b4.x; Bs[lk+1][lr] = b4.y;
        Bs[lk+2][lr] = b4.z; Bs[lk+3][lr] = b4.w;
        __syncthreads();

        #pragma unroll
        for (int k = 0; k < 8; k++) {
            float a[8], b[8];
            // split-tile fragments: rows ty*4..+3 and 64+ty*4..+3 (conflict-free quads)
            *(float4*)&a[0] = *(const float4*)&As[k][ty*4];
            *(float4*)&a[4] = *(const float4*)&As[k][64 + ty*4];
            *(float4*)&b[0] = *(const float4*)&Bs[k][tx*4];
            *(float4*)&b[4] = *(const float4*)&Bs[k][64 + tx*4];
            #pragma unroll
            for (int i = 0; i < 8; i++)
                #pragma unroll
                for (int j = 0; j < 8; j++)
                    acc[i][j] += a[i] * b[j];
        }
    }

    // write back: rows/cols per split-tile mapping
    #pragma unroll
    for (int i = 0; i < 8; i++) {
        int row = m0 + ((i < 4) ? (ty*4 + i) : (64 + ty*4 + (i - 4)));
        float4 c0 = make_float4(acc[i][0], acc[i][1], acc[i][2], acc[i][3]);
        float4 c1 = make_float4(acc[i][4], acc[i][5], acc[i][6], acc[i][7]);
        *(float4*)(C + (size_t)row * N + n0 + tx*4)      = c0;
        *(float4*)(C + (size_t)row * N + n0 + 64 + tx*4) = c1;
    }
}

// ---------------------------------------------------------------------------
// Flash attention, fp32, causal. Q/K/V layout: [S, H*HD] (head h at col h*64).
// Block: one (q-tile of 64 rows, head). 256 threads = 16x16.
// Thread (ty,tx): q rows ty*4+qi (both for scores and O), k cols tx+16*kk,
// O cols tx*4+di. Online softmax state (m,l) kept redundantly in registers
// by all 16 threads of a row group (16-lane shfl reductions).
// ---------------------------------------------------------------------------
#define KS_STRIDE 68
#define PS_STRIDE 68
// shared layout (floats)
#define SM_QS 0
#define SM_KS (SM_QS + 64*HD)          // 4096
#define SM_VS (SM_KS + 64*KS_STRIDE)   // 4096+4352
#define SM_PS (SM_VS + 64*HD)
#define SM_TOTAL_F (SM_PS + 64*PS_STRIDE)
#define ATTN_SMEM_BYTES (SM_TOTAL_F * 4)

__global__ __launch_bounds__(256) void attn_kernel(
    const float* __restrict__ Q, const float* __restrict__ K,
    const float* __restrict__ V, float* __restrict__ O)
{
    extern __shared__ float sm[];
    float* Qs = sm + SM_QS;
    float* Ks = sm + SM_KS;
    float* Vs = sm + SM_VS;
    float* Ps = sm + SM_PS;

    const int qt = blockIdx.x;   // 0..63
    const int h  = blockIdx.y;   // 0..15
    const int tid = threadIdx.x;
    const int ty = tid >> 4;
    const int tx = tid & 15;

    // load Q tile (coalesced, 64 rows x 16 float4)
    #pragma unroll
    for (int p = 0; p < 4; p++) {
        int i = tid + p * 256;
        int r = i >> 4, c4 = i & 15;
        *(float4*)&Qs[r*HD + c4*4] =
            *(const float4*)(Q + (size_t)(qt*64 + r) * D_MODEL + h*HD + c4*4);
    }

    float m_run[4], l_run[4], o[4][4];
    #pragma unroll
    for (int qi = 0; qi < 4; qi++) {
        m_run[qi] = -1e30f; l_run[qi] = 0.f;
        #pragma unroll
        for (int di = 0; di < 4; di++) o[qi][di] = 0.f;
    }

    for (int kt = 0; kt <= qt; kt++) {
        __syncthreads();   // prior PV reads of Ks/Vs/Ps done (covers Qs on iter 0 via next sync)
        // load K,V tiles
        #pragma unroll
        for (int p = 0; p < 4; p++) {
            int i = tid + p * 256;
            int r = i >> 4, c4 = i & 15;
            *(float4*)&Ks[r*KS_STRIDE + c4*4] =
                *(const float4*)(K + (size_t)(kt*64 + r) * D_MODEL + h*HD + c4*4);
            *(float4*)&Vs[r*HD + c4*4] =
                *(const float4*)(V + (size_t)(kt*64 + r) * D_MODEL + h*HD + c4*4);
        }
        __syncthreads();

        // scores: s[qi][kk] for q row ty*4+qi, k col tx+16*kk
        float s[4][4];
        #pragma unroll
        for (int qi = 0; qi < 4; qi++)
            #pragma unroll
            for (int kk = 0; kk < 4; kk++) s[qi][kk] = 0.f;

        #pragma unroll
        for (int d = 0; d < HD; d += 4) {
            float4 kf[4];
            #pragma unroll
            for (int kk = 0; kk < 4; kk++)
                kf[kk] = *(const float4*)&Ks[(tx + 16*kk)*KS_STRIDE + d];
            #pragma unroll
            for (int qi = 0; qi < 4; qi++) {
                float4 qf = *(const float4*)&Qs[(ty*4 + qi)*HD + d];
                #pragma unroll
                for (int kk = 0; kk < 4; kk++)
                    s[qi][kk] += qf.x*kf[kk].x + qf.y*kf[kk].y
                               + qf.z*kf[kk].z + qf.w*kf[kk].w;
            }
        }

        const bool diag = (kt == qt);
        #pragma unroll
        for (int qi = 0; qi < 4; qi++) {
            #pragma unroll
            for (int kk = 0; kk < 4; kk++) {
                float v = s[qi][kk] * SCALE;
                if (diag && (tx + 16*kk) > (ty*4 + qi)) v = -1e30f;
                s[qi][kk] = v;
            }
        }

        // online softmax per q row (16-lane reductions)
        #pragma unroll
        for (int qi = 0; qi < 4; qi++) {
            float mx = fmaxf(fmaxf(s[qi][0], s[qi][1]), fmaxf(s[qi][2], s[qi][3]));
            #pragma unroll
            for (int off = 8; off >= 1; off >>= 1)
                mx = fmaxf(mx, __shfl_xor_sync(0xffffffffu, mx, off));
            float mnew  = fmaxf(m_run[qi], mx);
            float alpha = __expf(m_run[qi] - mnew);
            float rs = 0.f;
            #pragma unroll
            for (int kk = 0; kk < 4; kk++) {
                float p = __expf(s[qi][kk] - mnew);
                s[qi][kk] = p; rs += p;
            }
            #pragma unroll
            for (int off = 8; off >= 1; off >>= 1)
                rs += __shfl_xor_sync(0xffffffffu, rs, off);
            l_run[qi] = l_run[qi] * alpha + rs;
            m_run[qi] = mnew;
            #pragma unroll
            for (int di = 0; di < 4; di++) o[qi][di] *= alpha;
        }

        // write P to shared
        #pragma unroll
        for (int qi = 0; qi < 4; qi++)
            #pragma unroll
            for (int kk = 0; kk < 4; kk++)
                Ps[(ty*4 + qi)*PS_STRIDE + tx + 16*kk] = s[qi][kk];
        __syncthreads();

        // O += P @ V  (thread: q rows ty*4+qi, d cols tx*4+di)
        #pragma unroll 8
        for (int k = 0; k < 64; k++) {
            float4 vv = *(const float4*)&Vs[k*HD + tx*4];
            float pq[4];
            #pragma unroll
            for (int qi = 0; qi < 4; qi++)
                pq[qi] = Ps[(ty*4 + qi)*PS_STRIDE + k];
            #pragma unroll
            for (int qi = 0; qi < 4; qi++) {
                o[qi][0] += pq[qi] * vv.x;
                o[qi][1] += pq[qi] * vv.y;
                o[qi][2] += pq[qi] * vv.z;
                o[qi][3] += pq[qi] * vv.w;
            }
        }
    }

    // normalize + store (layout [S, H*HD] -> feeds Wo GEMM directly)
    #pragma unroll
    for (int qi = 0; qi < 4; qi++) {
        float inv = 1.f / l_run[qi];
        float4 ov = make_float4(o[qi][0]*inv, o[qi][1]*inv, o[qi][2]*inv, o[qi][3]*inv);
        *(float4*)(O + (size_t)(qt*64 + ty*4 + qi) * D_MODEL + h*HD + tx*4) = ov;
    }
}

// ---------------------------------------------------------------------------
extern "C" void kernel_launch(void* const* d_in, const int* in_sizes, int n_in,
                              void* d_out, int out_size)
{
    const float* x  = (const float*)d_in[0];
    const float* Wq = (const float*)d_in[1];
    const float* Wk = (const float*)d_in[2];
    const float* Wv = (const float*)d_in[3];
    const float* Wo = (const float*)d_in[4];
    float* out = (float*)d_out;

    void *pq, *pk, *pv, *po;
    cudaGetSymbolAddress(&pq, g_Q);
    cudaGetSymbolAddress(&pk, g_K);
    cudaGetSymbolAddress(&pv, g_V);
    cudaGetSymbolAddress(&po, g_Ob);

    cudaFuncSetAttribute(attn_kernel,
                         cudaFuncAttributeMaxDynamicSharedMemorySize,
                         ATTN_SMEM_BYTES);

    dim3 gg(D_MODEL / 128, S_LEN / 128);   // (8, 32)
    sgemm_nt<<<gg, 256>>>(x, Wq, (float*)pq, S_LEN, D_MODEL, D_MODEL);
    sgemm_nt<<<gg, 256>>>(x, Wk, (float*)pk, S_LEN, D_MODEL, D_MODEL);
    sgemm_nt<<<gg, 256>>>(x, Wv, (float*)pv, S_LEN, D_MODEL, D_MODEL);

    dim3 ga(S_LEN / 64, N_HEADS);          // (64, 16)
    attn_kernel<<<ga, 256, ATTN_SMEM_BYTES>>>((const float*)pq, (const float*)pk,
                                              (const float*)pv, (float*)po);

    sgemm_nt<<<gg, 256>>>((const float*)po, Wo, out, S_LEN, D_MODEL, D_MODEL);
}

// round 3
// speedup vs baseline: 1.3244x; 1.3244x over previous
#include <cuda_runtime.h>
#include <cuda_bf16.h>
#include <cstdint>

#define S_LEN   4096
#define D_MODEL 1024
#define N_HEADS 16
#define HD      64
#define SCALE   0.125f

// ---------------------------------------------------------------------------
// Scratch (device globals: allocation-free)
// ---------------------------------------------------------------------------
__device__ __align__(16) float g_Q [S_LEN * D_MODEL];
__device__ __align__(16) float g_K [S_LEN * D_MODEL];
__device__ __align__(16) float g_V [S_LEN * D_MODEL];
__device__ __align__(16) float g_Ob[S_LEN * D_MODEL];

__device__ __align__(16) __nv_bfloat16 g_xh [S_LEN * D_MODEL];
__device__ __align__(16) __nv_bfloat16 g_xl [S_LEN * D_MODEL];
__device__ __align__(16) __nv_bfloat16 g_obh[S_LEN * D_MODEL];
__device__ __align__(16) __nv_bfloat16 g_obl[S_LEN * D_MODEL];
__device__ __align__(16) __nv_bfloat16 g_wqh[D_MODEL * D_MODEL];
__device__ __align__(16) __nv_bfloat16 g_wql[D_MODEL * D_MODEL];
__device__ __align__(16) __nv_bfloat16 g_wkh[D_MODEL * D_MODEL];
__device__ __align__(16) __nv_bfloat16 g_wkl[D_MODEL * D_MODEL];
__device__ __align__(16) __nv_bfloat16 g_wvh[D_MODEL * D_MODEL];
__device__ __align__(16) __nv_bfloat16 g_wvl[D_MODEL * D_MODEL];
__device__ __align__(16) __nv_bfloat16 g_woh[D_MODEL * D_MODEL];
__device__ __align__(16) __nv_bfloat16 g_wol[D_MODEL * D_MODEL];

// ---------------------------------------------------------------------------
// helpers
// ---------------------------------------------------------------------------
__device__ __forceinline__ uint32_t smem_u32(const void* p) {
    uint32_t a;
    asm("{ .reg .u64 t; cvta.to.shared.u64 t, %1; cvt.u32.u64 %0, t; }"
        : "=r"(a) : "l"(p));
    return a;
}

__device__ __forceinline__ void ldm_x4(uint32_t* r, uint32_t addr) {
    asm volatile("ldmatrix.sync.aligned.m8n8.x4.shared.b16 {%0,%1,%2,%3}, [%4];"
                 : "=r"(r[0]), "=r"(r[1]), "=r"(r[2]), "=r"(r[3]) : "r"(addr));
}

__device__ __forceinline__ void mma_bf16(float* c, const uint32_t* a,
                                         const uint32_t* b) {
    asm volatile(
        "mma.sync.aligned.m16n8k16.row.col.f32.bf16.bf16.f32 "
        "{%0,%1,%2,%3}, {%4,%5,%6,%7}, {%8,%9}, {%0,%1,%2,%3};"
        : "+f"(c[0]), "+f"(c[1]), "+f"(c[2]), "+f"(c[3])
        : "r"(a[0]), "r"(a[1]), "r"(a[2]), "r"(a[3]), "r"(b[0]), "r"(b[1]));
}

// ---------------------------------------------------------------------------
// fp32 -> (bf16 hi, bf16 lo) split
// ---------------------------------------------------------------------------
__global__ void split_kernel(const float* __restrict__ x,
                             __nv_bfloat16* __restrict__ h,
                             __nv_bfloat16* __restrict__ l, int n4)
{
    int i = blockIdx.x * blockDim.x + threadIdx.x;
    if (i >= n4) return;
    float4 v = ((const float4*)x)[i];
    __nv_bfloat16 h0 = __float2bfloat16_rn(v.x);
    __nv_bfloat16 h1 = __float2bfloat16_rn(v.y);
    __nv_bfloat16 h2 = __float2bfloat16_rn(v.z);
    __nv_bfloat16 h3 = __float2bfloat16_rn(v.w);
    __nv_bfloat16 l0 = __float2bfloat16_rn(v.x - __bfloat162float(h0));
    __nv_bfloat16 l1 = __float2bfloat16_rn(v.y - __bfloat162float(h1));
    __nv_bfloat16 l2 = __float2bfloat16_rn(v.z - __bfloat162float(h2));
    __nv_bfloat16 l3 = __float2bfloat16_rn(v.w - __bfloat162float(h3));
    __nv_bfloat162 hp0; hp0.x = h0; hp0.y = h1;
    __nv_bfloat162 hp1; hp1.x = h2; hp1.y = h3;
    __nv_bfloat162 lp0; lp0.x = l0; lp0.y = l1;
    __nv_bfloat162 lp1; lp1.x = l2; lp1.y = l3;
    ((__nv_bfloat162*)h)[2*i]   = hp0;
    ((__nv_bfloat162*)h)[2*i+1] = hp1;
    ((__nv_bfloat162*)l)[2*i]   = lp0;
    ((__nv_bfloat162*)l)[2*i+1] = lp1;
}

// ---------------------------------------------------------------------------
// C[M,N] = A @ B^T via mma.sync (HMMA), split-bf16: Ah*Bh + Ah*Bl + Al*Bh.
// CTA tile 128x128, 8 warps (4m x 2n, 32x64 each), BK=32, smem stride 40.
// ---------------------------------------------------------------------------
#define TSTRIDE 40   // bf16 elems per smem row (80 B): conflict-free ldmatrix

__global__ __launch_bounds__(256) void gemm_mma(
    const __nv_bfloat16* __restrict__ Ah, const __nv_bfloat16* __restrict__ Al,
    const __nv_bfloat16* __restrict__ Bh, const __nv_bfloat16* __restrict__ Bl,
    float* __restrict__ C, int M, int N, int K)
{
    __shared__ __align__(16) __nv_bfloat16 sAh[128 * TSTRIDE];
    __shared__ __align__(16) __nv_bfloat16 sAl[128 * TSTRIDE];
    __shared__ __align__(16) __nv_bfloat16 sBh[128 * TSTRIDE];
    __shared__ __align__(16) __nv_bfloat16 sBl[128 * TSTRIDE];

    const int tid  = threadIdx.x;
    const int lane = tid & 31;
    const int wid  = tid >> 5;
    const int wm   = wid & 3;        // 0..3  -> m offset wm*32
    const int wn   = wid >> 2;       // 0..1  -> n offset wn*64
    const int m0   = blockIdx.y * 128;
    const int n0   = blockIdx.x * 128;
    const int K4   = K >> 3;         // uint4 per row

    const uint4* gAh = (const uint4*)Ah;
    const uint4* gAl = (const uint4*)Al;
    const uint4* gBh = (const uint4*)Bh;
    const uint4* gBl = (const uint4*)Bl;

    // per-thread tile-load coords: idx = it*256+tid -> row idx>>2, seg idx&3
    const int r0 = (tid >> 2), seg = (tid & 3);
    // it=0 -> row r0, it=1 -> row r0+64

    float acc[2][8][4];
    #pragma unroll
    for (int mt = 0; mt < 2; mt++)
        #pragma unroll
        for (int nt = 0; nt < 8; nt++)
            #pragma unroll
            for (int e = 0; e < 4; e++) acc[mt][nt][e] = 0.f;

    // per-lane ldmatrix byte-offset pieces
    const int rr  = lane & 7;
    const int grp = lane >> 3;
    // A: row = mbase + (grp&1)*8 + rr, col = (grp>>1)*8 + kb
    const int aro = ((grp & 1) * 8 + rr);
    const int aco = (grp >> 1) * 8;
    // B: row = nbase + (grp>>1)*8 + rr, col = (grp&1)*8 + kb
    const int bro = ((grp >> 1) * 8 + rr);
    const int bco = (grp & 1) * 8;

    const uint32_t bAh = smem_u32(sAh), bAl = smem_u32(sAl);
    const uint32_t bBh = smem_u32(sBh), bBl = smem_u32(sBl);

    uint4 pf[4][2];

    // prefetch chunk 0
    #pragma unroll
    for (int it = 0; it < 2; it++) {
        int r = r0 + it * 64;
        size_t oa = (size_t)(m0 + r) * K4 + seg;
        size_t ob = (size_t)(n0 + r) * K4 + seg;
        pf[0][it] = gAh[oa]; pf[1][it] = gAl[oa];
        pf[2][it] = gBh[ob]; pf[3][it] = gBl[ob];
    }

    const int nchunks = K / 32;
    for (int c = 0; c < nchunks; ++c) {
        __syncthreads();
        #pragma unroll
        for (int it = 0; it < 2; it++) {
            int r = r0 + it * 64;
            int so = r * TSTRIDE + seg * 8;
            *(uint4*)&sAh[so] = pf[0][it];
            *(uint4*)&sAl[so] = pf[1][it];
            *(uint4*)&sBh[so] = pf[2][it];
            *(uint4*)&sBl[so] = pf[3][it];
        }
        __syncthreads();

        if (c + 1 < nchunks) {
            #pragma unroll
            for (int it = 0; it < 2; it++) {
                int r = r0 + it * 64;
                size_t oa = (size_t)(m0 + r) * K4 + (size_t)(c + 1) * 4 + seg;
                size_t ob = (size_t)(n0 + r) * K4 + (size_t)(c + 1) * 4 + seg;
                pf[0][it] = gAh[oa]; pf[1][it] = gAl[oa];
                pf[2][it] = gBh[ob]; pf[3][it] = gBl[ob];
            }
        }

        #pragma unroll
        for (int ks = 0; ks < 2; ks++) {
            const int kb = ks * 16;
            uint32_t ah[2][4], al[2][4], bh[4][4], bl[4][4];
            #pragma unroll
            for (int mt = 0; mt < 2; mt++) {
                int mbase = wm * 32 + mt * 16;
                uint32_t off = (uint32_t)(((mbase + aro) * TSTRIDE + aco + kb) * 2);
                ldm_x4(ah[mt], bAh + off);
                ldm_x4(al[mt], bAl + off);
            }
            #pragma unroll
            for (int np = 0; np < 4; np++) {
                int nbase = wn * 64 + np * 16;
                uint32_t off = (uint32_t)(((nbase + bro) * TSTRIDE + bco + kb) * 2);
                ldm_x4(bh[np], bBh + off);
                ldm_x4(bl[np], bBl + off);
            }
            #pragma unroll
            for (int mt = 0; mt < 2; mt++) {
                #pragma unroll
                for (int nt = 0; nt < 8; nt++) {
                    const uint32_t* ph = &bh[nt >> 1][(nt & 1) * 2];
                    const uint32_t* pl = &bl[nt >> 1][(nt & 1) * 2];
                    mma_bf16(acc[mt][nt], ah[mt], ph);   // Ah*Bh
                    mma_bf16(acc[mt][nt], ah[mt], pl);   // Ah*Bl
                    mma_bf16(acc[mt][nt], al[mt], ph);   // Al*Bh
                }
            }
        }
    }

    // epilogue: c0,c1 -> (row lane/4, col 2*(lane%4)); c2,c3 -> row+8
    #pragma unroll
    for (int mt = 0; mt < 2; mt++) {
        int rbase = m0 + wm * 32 + mt * 16 + (lane >> 2);
        #pragma unroll
        for (int nt = 0; nt < 8; nt++) {
            int cg = n0 + wn * 64 + nt * 8 + (lane & 3) * 2;
            float2 v0 = make_float2(acc[mt][nt][0], acc[mt][nt][1]);
            float2 v1 = make_float2(acc[mt][nt][2], acc[mt][nt][3]);
            *(float2*)(C + (size_t)rbase * N + cg)       = v0;
            *(float2*)(C + (size_t)(rbase + 8) * N + cg) = v1;
        }
    }
}

// ---------------------------------------------------------------------------
// Flash attention, fp32, causal (validated in R1)
// ---------------------------------------------------------------------------
#define KS_STRIDE 68
#define PS_STRIDE 68
#define SM_QS 0
#define SM_KS (SM_QS + 64*HD)
#define SM_VS (SM_KS + 64*KS_STRIDE)
#define SM_PS (SM_VS + 64*HD)
#define SM_TOTAL_F (SM_PS + 64*PS_STRIDE)
#define ATTN_SMEM_BYTES (SM_TOTAL_F * 4)

__global__ __launch_bounds__(256) void attn_kernel(
    const float* __restrict__ Q, const float* __restrict__ K,
    const float* __restrict__ V, float* __restrict__ O)
{
    extern __shared__ float smf[];
    float* Qs = smf + SM_QS;
    float* Ks = smf + SM_KS;
    float* Vs = smf + SM_VS;
    float* Ps = smf + SM_PS;

    const int qt = blockIdx.x;
    const int h  = blockIdx.y;
    const int tid = threadIdx.x;
    const int ty = tid >> 4;
    const int tx = tid & 15;

    #pragma unroll
    for (int p = 0; p < 4; p++) {
        int i = tid + p * 256;
        int r = i >> 4, c4 = i & 15;
        *(float4*)&Qs[r*HD + c4*4] =
            *(const float4*)(Q + (size_t)(qt*64 + r) * D_MODEL + h*HD + c4*4);
    }

    float m_run[4], l_run[4], o[4][4];
    #pragma unroll
    for (int qi = 0; qi < 4; qi++) {
        m_run[qi] = -1e30f; l_run[qi] = 0.f;
        #pragma unroll
        for (int di = 0; di < 4; di++) o[qi][di] = 0.f;
    }

    for (int kt = 0; kt <= qt; kt++) {
        __syncthreads();
        #pragma unroll
        for (int p = 0; p < 4; p++) {
            int i = tid + p * 256;
            int r = i >> 4, c4 = i & 15;
            *(float4*)&Ks[r*KS_STRIDE + c4*4] =
                *(const float4*)(K + (size_t)(kt*64 + r) * D_MODEL + h*HD + c4*4);
            *(float4*)&Vs[r*HD + c4*4] =
                *(const float4*)(V + (size_t)(kt*64 + r) * D_MODEL + h*HD + c4*4);
        }
        __syncthreads();

        float s[4][4];
        #pragma unroll
        for (int qi = 0; qi < 4; qi++)
            #pragma unroll
            for (int kk = 0; kk < 4; kk++) s[qi][kk] = 0.f;

        #pragma unroll
        for (int d = 0; d < HD; d += 4) {
            float4 kf[4];
            #pragma unroll
            for (int kk = 0; kk < 4; kk++)
                kf[kk] = *(const float4*)&Ks[(tx + 16*kk)*KS_STRIDE + d];
            #pragma unroll
            for (int qi = 0; qi < 4; qi++) {
                float4 qf = *(const float4*)&Qs[(ty*4 + qi)*HD + d];
                #pragma unroll
                for (int kk = 0; kk < 4; kk++)
                    s[qi][kk] += qf.x*kf[kk].x + qf.y*kf[kk].y
                               + qf.z*kf[kk].z + qf.w*kf[kk].w;
            }
        }

        const bool diag = (kt == qt);
        #pragma unroll
        for (int qi = 0; qi < 4; qi++) {
            #pragma unroll
            for (int kk = 0; kk < 4; kk++) {
                float v = s[qi][kk] * SCALE;
                if (diag && (tx + 16*kk) > (ty*4 + qi)) v = -1e30f;
                s[qi][kk] = v;
            }
        }

        #pragma unroll
        for (int qi = 0; qi < 4; qi++) {
            float mx = fmaxf(fmaxf(s[qi][0], s[qi][1]), fmaxf(s[qi][2], s[qi][3]));
            #pragma unroll
            for (int off = 8; off >= 1; off >>= 1)
                mx = fmaxf(mx, __shfl_xor_sync(0xffffffffu, mx, off));
            float mnew  = fmaxf(m_run[qi], mx);
            float alpha = __expf(m_run[qi] - mnew);
            float rs = 0.f;
            #pragma unroll
            for (int kk = 0; kk < 4; kk++) {
                float p = __expf(s[qi][kk] - mnew);
                s[qi][kk] = p; rs += p;
            }
            #pragma unroll
            for (int off = 8; off >= 1; off >>= 1)
                rs += __shfl_xor_sync(0xffffffffu, rs, off);
            l_run[qi] = l_run[qi] * alpha + rs;
            m_run[qi] = mnew;
            #pragma unroll
            for (int di = 0; di < 4; di++) o[qi][di] *= alpha;
        }

        #pragma unroll
        for (int qi = 0; qi < 4; qi++)
            #pragma unroll
            for (int kk = 0; kk < 4; kk++)
                Ps[(ty*4 + qi)*PS_STRIDE + tx + 16*kk] = s[qi][kk];
        __syncthreads();

        #pragma unroll 8
        for (int k = 0; k < 64; k++) {
            float4 vv = *(const float4*)&Vs[k*HD + tx*4];
            float pq[4];
            #pragma unroll
            for (int qi = 0; qi < 4; qi++)
                pq[qi] = Ps[(ty*4 + qi)*PS_STRIDE + k];
            #pragma unroll
            for (int qi = 0; qi < 4; qi++) {
                o[qi][0] += pq[qi] * vv.x;
                o[qi][1] += pq[qi] * vv.y;
                o[qi][2] += pq[qi] * vv.z;
                o[qi][3] += pq[qi] * vv.w;
            }
        }
    }

    #pragma unroll
    for (int qi = 0; qi < 4; qi++) {
        float inv = 1.f / l_run[qi];
        float4 ov = make_float4(o[qi][0]*inv, o[qi][1]*inv, o[qi][2]*inv, o[qi][3]*inv);
        *(float4*)(O + (size_t)(qt*64 + ty*4 + qi) * D_MODEL + h*HD + tx*4) = ov;
    }
}

// ---------------------------------------------------------------------------
extern "C" void kernel_launch(void* const* d_in, const int* in_sizes, int n_in,
                              void* d_out, int out_size)
{
    const float* x  = (const float*)d_in[0];
    const float* Wq = (const float*)d_in[1];
    const float* Wk = (const float*)d_in[2];
    const float* Wv = (const float*)d_in[3];
    const float* Wo = (const float*)d_in[4];
    float* out = (float*)d_out;

    void *pq, *pk, *pv, *po;
    void *pxh, *pxl, *pobh, *pobl;
    void *pwqh, *pwql, *pwkh, *pwkl, *pwvh, *pwvl, *pwoh, *pwol;
    cudaGetSymbolAddress(&pq, g_Q);   cudaGetSymbolAddress(&pk, g_K);
    cudaGetSymbolAddress(&pv, g_V);   cudaGetSymbolAddress(&po, g_Ob);
    cudaGetSymbolAddress(&pxh, g_xh); cudaGetSymbolAddress(&pxl, g_xl);
    cudaGetSymbolAddress(&pobh, g_obh); cudaGetSymbolAddress(&pobl, g_obl);
    cudaGetSymbolAddress(&pwqh, g_wqh); cudaGetSymbolAddress(&pwql, g_wql);
    cudaGetSymbolAddress(&pwkh, g_wkh); cudaGetSymbolAddress(&pwkl, g_wkl);
    cudaGetSymbolAddress(&pwvh, g_wvh); cudaGetSymbolAddress(&pwvl, g_wvl);
    cudaGetSymbolAddress(&pwoh, g_woh); cudaGetSymbolAddress(&pwol, g_wol);

    cudaFuncSetAttribute(attn_kernel,
                         cudaFuncAttributeMaxDynamicSharedMemorySize, ATTN_SMEM_BYTES);

    const int NX4 = S_LEN * D_MODEL / 4;     // 1048576
    const int NW4 = D_MODEL * D_MODEL / 4;   // 262144
    split_kernel<<<NX4/256, 256>>>(x,  (__nv_bfloat16*)pxh,  (__nv_bfloat16*)pxl,  NX4);
    split_kernel<<<NW4/256, 256>>>(Wq, (__nv_bfloat16*)pwqh, (__nv_bfloat16*)pwql, NW4);
    split_kernel<<<NW4/256, 256>>>(Wk, (__nv_bfloat16*)pwkh, (__nv_bfloat16*)pwkl, NW4);
    split_kernel<<<NW4/256, 256>>>(Wv, (__nv_bfloat16*)pwvh, (__nv_bfloat16*)pwvl, NW4);
    split_kernel<<<NW4/256, 256>>>(Wo, (__nv_bfloat16*)pwoh, (__nv_bfloat16*)pwol, NW4);

    dim3 gg(D_MODEL / 128, S_LEN / 128);   // (8, 32)
    gemm_mma<<<gg, 256>>>(
        (const __nv_bfloat16*)pxh, (const __nv_bfloat16*)pxl,
        (const __nv_bfloat16*)pwqh, (const __nv_bfloat16*)pwql,
        (float*)pq, S_LEN, D_MODEL, D_MODEL);
    gemm_mma<<<gg, 256>>>(
        (const __nv_bfloat16*)pxh, (const __nv_bfloat16*)pxl,
        (const __nv_bfloat16*)pwkh, (const __nv_bfloat16*)pwkl,
        (float*)pk, S_LEN, D_MODEL, D_MODEL);
    gemm_mma<<<gg, 256>>>(
        (const __nv_bfloat16*)pxh, (const __nv_bfloat16*)pxl,
        (const __nv_bfloat16*)pwvh, (const __nv_bfloat16*)pwvl,
        (float*)pv, S_LEN, D_MODEL, D_MODEL);

    dim3 ga(S_LEN / 64, N_HEADS);
    attn_kernel<<<ga, 256, ATTN_SMEM_BYTES>>>((const float*)pq, (const float*)pk,
                                              (const float*)pv, (float*)po);

    split_kernel<<<NX4/256, 256>>>((const float*)po,
                                   (__nv_bfloat16*)pobh, (__nv_bfloat16*)pobl, NX4);
    gemm_mma<<<gg, 256>>>(
        (const __nv_bfloat16*)pobh, (const __nv_bfloat16*)pobl,
        (const __nv_bfloat16*)pwoh, (const __nv_bfloat16*)pwol,
        out, S_LEN, D_MODEL, D_MODEL);
}

// round 4
// speedup vs baseline: 2.5853x; 1.9521x over previous
#include <cuda_runtime.h>
#include <cuda_bf16.h>
#include <cstdint>

#define S_LEN   4096
#define D_MODEL 1024
#define N_HEADS 16
#define HD      64
#define SCALE   0.125f

// ---------------------------------------------------------------------------
// Scratch (device globals: allocation-free)
// ---------------------------------------------------------------------------
__device__ __align__(16) float g_Q [S_LEN * D_MODEL];
__device__ __align__(16) float g_K [S_LEN * D_MODEL];
__device__ __align__(16) float g_V [S_LEN * D_MODEL];

__device__ __align__(16) __nv_bfloat16 g_xh [S_LEN * D_MODEL];
__device__ __align__(16) __nv_bfloat16 g_xl [S_LEN * D_MODEL];
__device__ __align__(16) __nv_bfloat16 g_obh[S_LEN * D_MODEL];
__device__ __align__(16) __nv_bfloat16 g_obl[S_LEN * D_MODEL];
__device__ __align__(16) __nv_bfloat16 g_qh [S_LEN * D_MODEL];
__device__ __align__(16) __nv_bfloat16 g_ql [S_LEN * D_MODEL];
__device__ __align__(16) __nv_bfloat16 g_kh [S_LEN * D_MODEL];
__device__ __align__(16) __nv_bfloat16 g_kl [S_LEN * D_MODEL];
__device__ __align__(16) __nv_bfloat16 g_vh [S_LEN * D_MODEL];
__device__ __align__(16) __nv_bfloat16 g_vl [S_LEN * D_MODEL];
__device__ __align__(16) __nv_bfloat16 g_wqh[D_MODEL * D_MODEL];
__device__ __align__(16) __nv_bfloat16 g_wql[D_MODEL * D_MODEL];
__device__ __align__(16) __nv_bfloat16 g_wkh[D_MODEL * D_MODEL];
__device__ __align__(16) __nv_bfloat16 g_wkl[D_MODEL * D_MODEL];
__device__ __align__(16) __nv_bfloat16 g_wvh[D_MODEL * D_MODEL];
__device__ __align__(16) __nv_bfloat16 g_wvl[D_MODEL * D_MODEL];
__device__ __align__(16) __nv_bfloat16 g_woh[D_MODEL * D_MODEL];
__device__ __align__(16) __nv_bfloat16 g_wol[D_MODEL * D_MODEL];

// ---------------------------------------------------------------------------
// helpers
// ---------------------------------------------------------------------------
__device__ __forceinline__ uint32_t smem_u32(const void* p) {
    uint32_t a;
    asm("{ .reg .u64 t; cvta.to.shared.u64 t, %1; cvt.u32.u64 %0, t; }"
        : "=r"(a) : "l"(p));
    return a;
}

__device__ __forceinline__ void ldm_x4(uint32_t* r, uint32_t addr) {
    asm volatile("ldmatrix.sync.aligned.m8n8.x4.shared.b16 {%0,%1,%2,%3}, [%4];"
                 : "=r"(r[0]), "=r"(r[1]), "=r"(r[2]), "=r"(r[3]) : "r"(addr));
}
__device__ __forceinline__ void ldm_x4_t(uint32_t* r, uint32_t addr) {
    asm volatile("ldmatrix.sync.aligned.m8n8.x4.trans.shared.b16 {%0,%1,%2,%3}, [%4];"
                 : "=r"(r[0]), "=r"(r[1]), "=r"(r[2]), "=r"(r[3]) : "r"(addr));
}

__device__ __forceinline__ void mma_bf16(float* c, const uint32_t* a,
                                         const uint32_t* b) {
    asm volatile(
        "mma.sync.aligned.m16n8k16.row.col.f32.bf16.bf16.f32 "
        "{%0,%1,%2,%3}, {%4,%5,%6,%7}, {%8,%9}, {%0,%1,%2,%3};"
        : "+f"(c[0]), "+f"(c[1]), "+f"(c[2]), "+f"(c[3])
        : "r"(a[0]), "r"(a[1]), "r"(a[2]), "r"(a[3]), "r"(b[0]), "r"(b[1]));
}

__device__ __forceinline__ void split_pack(float x, float y,
                                           uint32_t& hi, uint32_t& lo) {
    __nv_bfloat16 hx = __float2bfloat16_rn(x), hy = __float2bfloat16_rn(y);
    __nv_bfloat16 lx = __float2bfloat16_rn(x - __bfloat162float(hx));
    __nv_bfloat16 ly = __float2bfloat16_rn(y - __bfloat162float(hy));
    __nv_bfloat162 hp; hp.x = hx; hp.y = hy;
    __nv_bfloat162 lp; lp.x = lx; lp.y = ly;
    hi = *(uint32_t*)&hp; lo = *(uint32_t*)&lp;
}

// ---------------------------------------------------------------------------
// fp32 -> (bf16 hi, bf16 lo) split
// ---------------------------------------------------------------------------
__global__ void split_kernel(const float* __restrict__ x,
                             __nv_bfloat16* __restrict__ h,
                             __nv_bfloat16* __restrict__ l, int n4)
{
    int i = blockIdx.x * blockDim.x + threadIdx.x;
    if (i >= n4) return;
    float4 v = ((const float4*)x)[i];
    uint32_t h0, l0, h1, l1;
    split_pack(v.x, v.y, h0, l0);
    split_pack(v.z, v.w, h1, l1);
    ((uint32_t*)h)[2*i]   = h0;
    ((uint32_t*)h)[2*i+1] = h1;
    ((uint32_t*)l)[2*i]   = l0;
    ((uint32_t*)l)[2*i+1] = l1;
}

// ---------------------------------------------------------------------------
// C[M,N] = A @ B^T via HMMA, split-bf16 (unchanged from R3)
// ---------------------------------------------------------------------------
#define TSTRIDE 40

__global__ __launch_bounds__(256) void gemm_mma(
    const __nv_bfloat16* __restrict__ Ah, const __nv_bfloat16* __restrict__ Al,
    const __nv_bfloat16* __restrict__ Bh, const __nv_bfloat16* __restrict__ Bl,
    float* __restrict__ C, int M, int N, int K)
{
    __shared__ __align__(16) __nv_bfloat16 sAh[128 * TSTRIDE];
    __shared__ __align__(16) __nv_bfloat16 sAl[128 * TSTRIDE];
    __shared__ __align__(16) __nv_bfloat16 sBh[128 * TSTRIDE];
    __shared__ __align__(16) __nv_bfloat16 sBl[128 * TSTRIDE];

    const int tid  = threadIdx.x;
    const int lane = tid & 31;
    const int wid  = tid >> 5;
    const int wm   = wid & 3;
    const int wn   = wid >> 2;
    const int m0   = blockIdx.y * 128;
    const int n0   = blockIdx.x * 128;
    const int K4   = K >> 3;

    const uint4* gAh = (const uint4*)Ah;
    const uint4* gAl = (const uint4*)Al;
    const uint4* gBh = (const uint4*)Bh;
    const uint4* gBl = (const uint4*)Bl;

    const int r0 = (tid >> 2), seg = (tid & 3);

    float acc[2][8][4];
    #pragma unroll
    for (int mt = 0; mt < 2; mt++)
        #pragma unroll
        for (int nt = 0; nt < 8; nt++)
            #pragma unroll
            for (int e = 0; e < 4; e++) acc[mt][nt][e] = 0.f;

    const int rr  = lane & 7;
    const int grp = lane >> 3;
    const int aro = ((grp & 1) * 8 + rr);
    const int aco = (grp >> 1) * 8;
    const int bro = ((grp >> 1) * 8 + rr);
    const int bco = (grp & 1) * 8;

    const uint32_t bAh = smem_u32(sAh), bAl = smem_u32(sAl);
    const uint32_t bBh = smem_u32(sBh), bBl = smem_u32(sBl);

    uint4 pf[4][2];
    #pragma unroll
    for (int it = 0; it < 2; it++) {
        int r = r0 + it * 64;
        size_t oa = (size_t)(m0 + r) * K4 + seg;
        size_t ob = (size_t)(n0 + r) * K4 + seg;
        pf[0][it] = gAh[oa]; pf[1][it] = gAl[oa];
        pf[2][it] = gBh[ob]; pf[3][it] = gBl[ob];
    }

    const int nchunks = K / 32;
    for (int c = 0; c < nchunks; ++c) {
        __syncthreads();
        #pragma unroll
        for (int it = 0; it < 2; it++) {
            int r = r0 + it * 64;
            int so = r * TSTRIDE + seg * 8;
            *(uint4*)&sAh[so] = pf[0][it];
            *(uint4*)&sAl[so] = pf[1][it];
            *(uint4*)&sBh[so] = pf[2][it];
            *(uint4*)&sBl[so] = pf[3][it];
        }
        __syncthreads();

        if (c + 1 < nchunks) {
            #pragma unroll
            for (int it = 0; it < 2; it++) {
                int r = r0 + it * 64;
                size_t oa = (size_t)(m0 + r) * K4 + (size_t)(c + 1) * 4 + seg;
                size_t ob = (size_t)(n0 + r) * K4 + (size_t)(c + 1) * 4 + seg;
                pf[0][it] = gAh[oa]; pf[1][it] = gAl[oa];
                pf[2][it] = gBh[ob]; pf[3][it] = gBl[ob];
            }
        }

        #pragma unroll
        for (int ks = 0; ks < 2; ks++) {
            const int kb = ks * 16;
            uint32_t ah[2][4], al[2][4], bh[4][4], bl[4][4];
            #pragma unroll
            for (int mt = 0; mt < 2; mt++) {
                int mbase = wm * 32 + mt * 16;
                uint32_t off = (uint32_t)(((mbase + aro) * TSTRIDE + aco + kb) * 2);
                ldm_x4(ah[mt], bAh + off);
                ldm_x4(al[mt], bAl + off);
            }
            #pragma unroll
            for (int np = 0; np < 4; np++) {
                int nbase = wn * 64 + np * 16;
                uint32_t off = (uint32_t)(((nbase + bro) * TSTRIDE + bco + kb) * 2);
                ldm_x4(bh[np], bBh + off);
                ldm_x4(bl[np], bBl + off);
            }
            #pragma unroll
            for (int mt = 0; mt < 2; mt++) {
                #pragma unroll
                for (int nt = 0; nt < 8; nt++) {
                    const uint32_t* ph = &bh[nt >> 1][(nt & 1) * 2];
                    const uint32_t* pl = &bl[nt >> 1][(nt & 1) * 2];
                    mma_bf16(acc[mt][nt], ah[mt], ph);
                    mma_bf16(acc[mt][nt], ah[mt], pl);
                    mma_bf16(acc[mt][nt], al[mt], ph);
                }
            }
        }
    }

    #pragma unroll
    for (int mt = 0; mt < 2; mt++) {
        int rbase = m0 + wm * 32 + mt * 16 + (lane >> 2);
        #pragma unroll
        for (int nt = 0; nt < 8; nt++) {
            int cg = n0 + wn * 64 + nt * 8 + (lane & 3) * 2;
            float2 v0 = make_float2(acc[mt][nt][0], acc[mt][nt][1]);
            float2 v1 = make_float2(acc[mt][nt][2], acc[mt][nt][3]);
            *(float2*)(C + (size_t)rbase * N + cg)       = v0;
            *(float2*)(C + (size_t)(rbase + 8) * N + cg) = v1;
        }
    }
}

// ---------------------------------------------------------------------------
// Flash attention on HMMA, split-bf16. CTA = (64-row q tile, head), 4 warps.
// Each warp: 16 q rows. QK^T = Qh*Kh + Qh*Kl + Ql*Kh; softmax fp32 in regs;
// PV = Ph*Vh + Ph*Vl + Pl*Vh with P split done in registers.
// Output written pre-split (Oh/Ol bf16) for the Wo GEMM.
// ---------------------------------------------------------------------------
#define AST 72   // bf16 smem row stride (144B): conflict-free ldmatrix

__global__ __launch_bounds__(128) void attn_mma(
    const __nv_bfloat16* __restrict__ Qh, const __nv_bfloat16* __restrict__ Ql,
    const __nv_bfloat16* __restrict__ Kh, const __nv_bfloat16* __restrict__ Kl,
    const __nv_bfloat16* __restrict__ Vh, const __nv_bfloat16* __restrict__ Vl,
    __nv_bfloat16* __restrict__ Oh, __nv_bfloat16* __restrict__ Ol)
{
    __shared__ __align__(16) __nv_bfloat16 sQh[64*AST], sQl[64*AST];
    __shared__ __align__(16) __nv_bfloat16 sKh[64*AST], sKl[64*AST];
    __shared__ __align__(16) __nv_bfloat16 sVh[64*AST], sVl[64*AST];

    const int qt = blockIdx.x, h = blockIdx.y;
    const int tid = threadIdx.x, lane = tid & 31, wid = tid >> 5;
    const int rr = lane & 7, grp = lane >> 3;
    const int aro = (grp & 1) * 8 + rr, aco = (grp >> 1) * 8;  // A-frag addr
    const int bro = (grp >> 1) * 8 + rr, bco = (grp & 1) * 8;  // B-frag addr

    // ---- load Q tile (64 x 64 bf16 hi/lo) ----
    #pragma unroll
    for (int it = 0; it < 4; it++) {
        int idx = it * 128 + tid;
        int row = idx >> 3, seg = idx & 7;
        size_t go = (size_t)(qt*64 + row) * D_MODEL + h*HD;
        *(uint4*)&sQh[row*AST + seg*8] = ((const uint4*)(Qh + go))[seg];
        *(uint4*)&sQl[row*AST + seg*8] = ((const uint4*)(Ql + go))[seg];
    }
    __syncthreads();

    // ---- Q fragments held in registers for all k-tiles ----
    uint32_t qfh[4][4], qfl[4][4];
    {
        const uint32_t bQh = smem_u32(sQh), bQl = smem_u32(sQl);
        #pragma unroll
        for (int ks = 0; ks < 4; ks++) {
            uint32_t off = (uint32_t)(((wid*16 + aro) * AST + aco + ks*16) * 2);
            ldm_x4(qfh[ks], bQh + off);
            ldm_x4(qfl[ks], bQl + off);
        }
    }

    float m0 = -1e30f, m1 = -1e30f, l0 = 0.f, l1 = 0.f;
    float o[8][4];
    #pragma unroll
    for (int nt = 0; nt < 8; nt++)
        #pragma unroll
        for (int e = 0; e < 4; e++) o[nt][e] = 0.f;

    const uint32_t bKh = smem_u32(sKh), bKl = smem_u32(sKl);
    const uint32_t bVh = smem_u32(sVh), bVl = smem_u32(sVl);

    for (int kt = 0; kt <= qt; kt++) {
        __syncthreads();
        #pragma unroll
        for (int it = 0; it < 4; it++) {
            int idx = it * 128 + tid;
            int row = idx >> 3, seg = idx & 7;
            size_t go = (size_t)(kt*64 + row) * D_MODEL + h*HD;
            *(uint4*)&sKh[row*AST + seg*8] = ((const uint4*)(Kh + go))[seg];
            *(uint4*)&sKl[row*AST + seg*8] = ((const uint4*)(Kl + go))[seg];
            *(uint4*)&sVh[row*AST + seg*8] = ((const uint4*)(Vh + go))[seg];
            *(uint4*)&sVl[row*AST + seg*8] = ((const uint4*)(Vl + go))[seg];
        }
        __syncthreads();

        // ---- QK^T ----
        float s[8][4];
        #pragma unroll
        for (int nt = 0; nt < 8; nt++)
            #pragma unroll
            for (int e = 0; e < 4; e++) s[nt][e] = 0.f;

        #pragma unroll
        for (int ks = 0; ks < 4; ks++) {
            uint32_t kfh[4][4], kfl[4][4];
            #pragma unroll
            for (int np = 0; np < 4; np++) {
                uint32_t off = (uint32_t)(((np*16 + bro) * AST + bco + ks*16) * 2);
                ldm_x4(kfh[np], bKh + off);
                ldm_x4(kfl[np], bKl + off);
            }
            #pragma unroll
            for (int np = 0; np < 4; np++)
                #pragma unroll
                for (int hf = 0; hf < 2; hf++) {
                    int nt = np*2 + hf;
                    mma_bf16(s[nt], qfh[ks], &kfh[np][hf*2]);
                    mma_bf16(s[nt], qfh[ks], &kfl[np][hf*2]);
                    mma_bf16(s[nt], qfl[ks], &kfh[np][hf*2]);
                }
        }

        // ---- scale + causal mask (diagonal tile only) ----
        const bool diag = (kt == qt);
        const int r_in  = wid*16 + (lane >> 2);
        const int cbase = 2*(lane & 3);
        #pragma unroll
        for (int nt = 0; nt < 8; nt++) {
            #pragma unroll
            for (int e = 0; e < 4; e++) {
                float v = s[nt][e] * SCALE;
                if (diag) {
                    int c = nt*8 + cbase + (e & 1);
                    int r = r_in + (e >> 1) * 8;
                    if (c > r) v = -1e30f;
                }
                s[nt][e] = v;
            }
        }

        // ---- online softmax (rows r_in and r_in+8) ----
        float mx0 = -1e30f, mx1 = -1e30f;
        #pragma unroll
        for (int nt = 0; nt < 8; nt++) {
            mx0 = fmaxf(mx0, fmaxf(s[nt][0], s[nt][1]));
            mx1 = fmaxf(mx1, fmaxf(s[nt][2], s[nt][3]));
        }
        mx0 = fmaxf(mx0, __shfl_xor_sync(0xffffffffu, mx0, 1));
        mx0 = fmaxf(mx0, __shfl_xor_sync(0xffffffffu, mx0, 2));
        mx1 = fmaxf(mx1, __shfl_xor_sync(0xffffffffu, mx1, 1));
        mx1 = fmaxf(mx1, __shfl_xor_sync(0xffffffffu, mx1, 2));

        float mn0 = fmaxf(m0, mx0), mn1 = fmaxf(m1, mx1);
        float a0 = __expf(m0 - mn0), a1 = __expf(m1 - mn1);
        float rs0 = 0.f, rs1 = 0.f;
        #pragma unroll
        for (int nt = 0; nt < 8; nt++) {
            s[nt][0] = __expf(s[nt][0] - mn0);
            s[nt][1] = __expf(s[nt][1] - mn0);
            s[nt][2] = __expf(s[nt][2] - mn1);
            s[nt][3] = __expf(s[nt][3] - mn1);
            rs0 += s[nt][0] + s[nt][1];
            rs1 += s[nt][2] + s[nt][3];
        }
        rs0 += __shfl_xor_sync(0xffffffffu, rs0, 1);
        rs0 += __shfl_xor_sync(0xffffffffu, rs0, 2);
        rs1 += __shfl_xor_sync(0xffffffffu, rs1, 1);
        rs1 += __shfl_xor_sync(0xffffffffu, rs1, 2);

        l0 = l0 * a0 + rs0;  l1 = l1 * a1 + rs1;
        m0 = mn0;            m1 = mn1;
        #pragma unroll
        for (int nt = 0; nt < 8; nt++) {
            o[nt][0] *= a0; o[nt][1] *= a0;
            o[nt][2] *= a1; o[nt][3] *= a1;
        }

        // ---- P -> A fragments (register-only), split hi/lo ----
        uint32_t aph[4][4], apl[4][4];
        #pragma unroll
        for (int t = 0; t < 4; t++) {
            split_pack(s[2*t  ][0], s[2*t  ][1], aph[t][0], apl[t][0]);
            split_pack(s[2*t  ][2], s[2*t  ][3], aph[t][1], apl[t][1]);
            split_pack(s[2*t+1][0], s[2*t+1][1], aph[t][2], apl[t][2]);
            split_pack(s[2*t+1][2], s[2*t+1][3], aph[t][3], apl[t][3]);
        }

        // ---- O += P @ V ----
        #pragma unroll
        for (int ks = 0; ks < 4; ks++) {
            #pragma unroll
            for (int np = 0; np < 4; np++) {
                uint32_t vfh[4], vfl[4];
                uint32_t off = (uint32_t)(((ks*16 + (grp & 1)*8 + rr) * AST
                                           + np*16 + (grp >> 1)*8) * 2);
                ldm_x4_t(vfh, bVh + off);
                ldm_x4_t(vfl, bVl + off);
                #pragma unroll
                for (int hf = 0; hf < 2; hf++) {
                    int nt = np*2 + hf;
                    mma_bf16(o[nt], aph[ks], &vfh[hf*2]);
                    mma_bf16(o[nt], aph[ks], &vfl[hf*2]);
                    mma_bf16(o[nt], apl[ks], &vfh[hf*2]);
                }
            }
        }
    }

    // ---- epilogue: normalize + write pre-split bf16 hi/lo ----
    float inv0 = 1.f / l0, inv1 = 1.f / l1;
    int row0 = qt*64 + wid*16 + (lane >> 2);
    #pragma unroll
    for (int nt = 0; nt < 8; nt++) {
        int col = h*HD + nt*8 + 2*(lane & 3);
        uint32_t hh, ll;
        split_pack(o[nt][0]*inv0, o[nt][1]*inv0, hh, ll);
        *(uint32_t*)&Oh[(size_t)row0 * D_MODEL + col] = hh;
        *(uint32_t*)&Ol[(size_t)row0 * D_MODEL + col] = ll;
        split_pack(o[nt][2]*inv1, o[nt][3]*inv1, hh, ll);
        *(uint32_t*)&Oh[(size_t)(row0+8) * D_MODEL + col] = hh;
        *(uint32_t*)&Ol[(size_t)(row0+8) * D_MODEL + col] = ll;
    }
}

// ---------------------------------------------------------------------------
extern "C" void kernel_launch(void* const* d_in, const int* in_sizes, int n_in,
                              void* d_out, int out_size)
{
    const float* x  = (const float*)d_in[0];
    const float* Wq = (const float*)d_in[1];
    const float* Wk = (const float*)d_in[2];
    const float* Wv = (const float*)d_in[3];
    const float* Wo = (const float*)d_in[4];
    float* out = (float*)d_out;

    void *pq, *pk, *pv;
    void *pxh, *pxl, *pobh, *pobl;
    void *pqh, *pql, *pkh, *pkl, *pvh, *pvl;
    void *pwqh, *pwql, *pwkh, *pwkl, *pwvh, *pwvl, *pwoh, *pwol;
    cudaGetSymbolAddress(&pq, g_Q);   cudaGetSymbolAddress(&pk, g_K);
    cudaGetSymbolAddress(&pv, g_V);
    cudaGetSymbolAddress(&pxh, g_xh); cudaGetSymbolAddress(&pxl, g_xl);
    cudaGetSymbolAddress(&pobh, g_obh); cudaGetSymbolAddress(&pobl, g_obl);
    cudaGetSymbolAddress(&pqh, g_qh); cudaGetSymbolAddress(&pql, g_ql);
    cudaGetSymbolAddress(&pkh, g_kh); cudaGetSymbolAddress(&pkl, g_kl);
    cudaGetSymbolAddress(&pvh, g_vh); cudaGetSymbolAddress(&pvl, g_vl);
    cudaGetSymbolAddress(&pwqh, g_wqh); cudaGetSymbolAddress(&pwql, g_wql);
    cudaGetSymbolAddress(&pwkh, g_wkh); cudaGetSymbolAddress(&pwkl, g_wkl);
    cudaGetSymbolAddress(&pwvh, g_wvh); cudaGetSymbolAddress(&pwvl, g_wvl);
    cudaGetSymbolAddress(&pwoh, g_woh); cudaGetSymbolAddress(&pwol, g_wol);

    const int NX4 = S_LEN * D_MODEL / 4;
    const int NW4 = D_MODEL * D_MODEL / 4;
    split_kernel<<<NX4/256, 256>>>(x,  (__nv_bfloat16*)pxh,  (__nv_bfloat16*)pxl,  NX4);
    split_kernel<<<NW4/256, 256>>>(Wq, (__nv_bfloat16*)pwqh, (__nv_bfloat16*)pwql, NW4);
    split_kernel<<<NW4/256, 256>>>(Wk, (__nv_bfloat16*)pwkh, (__nv_bfloat16*)pwkl, NW4);
    split_kernel<<<NW4/256, 256>>>(Wv, (__nv_bfloat16*)pwvh, (__nv_bfloat16*)pwvl, NW4);
    split_kernel<<<NW4/256, 256>>>(Wo, (__nv_bfloat16*)pwoh, (__nv_bfloat16*)pwol, NW4);

    dim3 gg(D_MODEL / 128, S_LEN / 128);   // (8, 32)
    gemm_mma<<<gg, 256>>>(
        (const __nv_bfloat16*)pxh, (const __nv_bfloat16*)pxl,
        (const __nv_bfloat16*)pwqh, (const __nv_bfloat16*)pwql,
        (float*)pq, S_LEN, D_MODEL, D_MODEL);
    gemm_mma<<<gg, 256>>>(
        (const __nv_bfloat16*)pxh, (const __nv_bfloat16*)pxl,
        (const __nv_bfloat16*)pwkh, (const __nv_bfloat16*)pwkl,
        (float*)pk, S_LEN, D_MODEL, D_MODEL);
    gemm_mma<<<gg, 256>>>(
        (const __nv_bfloat16*)pxh, (const __nv_bfloat16*)pxl,
        (const __nv_bfloat16*)pwvh, (const __nv_bfloat16*)pwvl,
        (float*)pv, S_LEN, D_MODEL, D_MODEL);

    split_kernel<<<NX4/256, 256>>>((const float*)pq,
                                   (__nv_bfloat16*)pqh, (__nv_bfloat16*)pql, NX4);
    split_kernel<<<NX4/256, 256>>>((const float*)pk,
                                   (__nv_bfloat16*)pkh, (__nv_bfloat16*)pkl, NX4);
    split_kernel<<<NX4/256, 256>>>((const float*)pv,
                                   (__nv_bfloat16*)pvh, (__nv_bfloat16*)pvl, NX4);

    dim3 ga(S_LEN / 64, N_HEADS);          // (64, 16)
    attn_mma<<<ga, 128>>>(
        (const __nv_bfloat16*)pqh, (const __nv_bfloat16*)pql,
        (const __nv_bfloat16*)pkh, (const __nv_bfloat16*)pkl,
        (const __nv_bfloat16*)pvh, (const __nv_bfloat16*)pvl,
        (__nv_bfloat16*)pobh, (__nv_bfloat16*)pobl);

    gemm_mma<<<gg, 256>>>(
        (const __nv_bfloat16*)pobh, (const __nv_bfloat16*)pobl,
        (const __nv_bfloat16*)pwoh, (const __nv_bfloat16*)pwol,
        out, S_LEN, D_MODEL, D_MODEL);
}

// round 5
// speedup vs baseline: 2.7436x; 1.0613x over previous
#include <cuda_runtime.h>
#include <cuda_bf16.h>
#include <cstdint>

#define S_LEN   4096
#define D_MODEL 1024
#define N_HEADS 16
#define HD      64
#define SCALE   0.125f

// ---------------------------------------------------------------------------
// Scratch (device globals: allocation-free)
// ---------------------------------------------------------------------------
__device__ __align__(16) __nv_bfloat16 g_xh [S_LEN * D_MODEL];
__device__ __align__(16) __nv_bfloat16 g_xl [S_LEN * D_MODEL];
__device__ __align__(16) __nv_bfloat16 g_obh[S_LEN * D_MODEL];
__device__ __align__(16) __nv_bfloat16 g_obl[S_LEN * D_MODEL];
__device__ __align__(16) __nv_bfloat16 g_qh [S_LEN * D_MODEL];
__device__ __align__(16) __nv_bfloat16 g_ql [S_LEN * D_MODEL];
__device__ __align__(16) __nv_bfloat16 g_kh [S_LEN * D_MODEL];
__device__ __align__(16) __nv_bfloat16 g_kl [S_LEN * D_MODEL];
__device__ __align__(16) __nv_bfloat16 g_vh [S_LEN * D_MODEL];
__device__ __align__(16) __nv_bfloat16 g_vl [S_LEN * D_MODEL];
__device__ __align__(16) __nv_bfloat16 g_wqh[D_MODEL * D_MODEL];
__device__ __align__(16) __nv_bfloat16 g_wql[D_MODEL * D_MODEL];
__device__ __align__(16) __nv_bfloat16 g_wkh[D_MODEL * D_MODEL];
__device__ __align__(16) __nv_bfloat16 g_wkl[D_MODEL * D_MODEL];
__device__ __align__(16) __nv_bfloat16 g_wvh[D_MODEL * D_MODEL];
__device__ __align__(16) __nv_bfloat16 g_wvl[D_MODEL * D_MODEL];
__device__ __align__(16) __nv_bfloat16 g_woh[D_MODEL * D_MODEL];
__device__ __align__(16) __nv_bfloat16 g_wol[D_MODEL * D_MODEL];

// ---------------------------------------------------------------------------
// helpers
// ---------------------------------------------------------------------------
__device__ __forceinline__ uint32_t smem_u32(const void* p) {
    uint32_t a;
    asm("{ .reg .u64 t; cvta.to.shared.u64 t, %1; cvt.u32.u64 %0, t; }"
        : "=r"(a) : "l"(p));
    return a;
}

__device__ __forceinline__ void ldm_x4(uint32_t* r, uint32_t addr) {
    asm volatile("ldmatrix.sync.aligned.m8n8.x4.shared.b16 {%0,%1,%2,%3}, [%4];"
                 : "=r"(r[0]), "=r"(r[1]), "=r"(r[2]), "=r"(r[3]) : "r"(addr));
}
__device__ __forceinline__ void ldm_x4_t(uint32_t* r, uint32_t addr) {
    asm volatile("ldmatrix.sync.aligned.m8n8.x4.trans.shared.b16 {%0,%1,%2,%3}, [%4];"
                 : "=r"(r[0]), "=r"(r[1]), "=r"(r[2]), "=r"(r[3]) : "r"(addr));
}

__device__ __forceinline__ void mma_bf16(float* c, const uint32_t* a,
                                         const uint32_t* b) {
    asm volatile(
        "mma.sync.aligned.m16n8k16.row.col.f32.bf16.bf16.f32 "
        "{%0,%1,%2,%3}, {%4,%5,%6,%7}, {%8,%9}, {%0,%1,%2,%3};"
        : "+f"(c[0]), "+f"(c[1]), "+f"(c[2]), "+f"(c[3])
        : "r"(a[0]), "r"(a[1]), "r"(a[2]), "r"(a[3]), "r"(b[0]), "r"(b[1]));
}

__device__ __forceinline__ void split_pack(float x, float y,
                                           uint32_t& hi, uint32_t& lo) {
    __nv_bfloat16 hx = __float2bfloat16_rn(x), hy = __float2bfloat16_rn(y);
    __nv_bfloat16 lx = __float2bfloat16_rn(x - __bfloat162float(hx));
    __nv_bfloat16 ly = __float2bfloat16_rn(y - __bfloat162float(hy));
    __nv_bfloat162 hp; hp.x = hx; hp.y = hy;
    __nv_bfloat162 lp; lp.x = lx; lp.y = ly;
    hi = *(uint32_t*)&hp; lo = *(uint32_t*)&lp;
}

#define CP_ASYNC16(saddr, gptr) \
    asm volatile("cp.async.cg.shared.global [%0], [%1], 16;" :: "r"(saddr), "l"(gptr))
#define CP_COMMIT() asm volatile("cp.async.commit_group;" ::: "memory")
#define CP_WAIT1()  asm volatile("cp.async.wait_group 1;" ::: "memory")

// ---------------------------------------------------------------------------
// fp32 -> (bf16 hi, bf16 lo) split
// ---------------------------------------------------------------------------
__global__ void split_kernel(const float* __restrict__ x,
                             __nv_bfloat16* __restrict__ h,
                             __nv_bfloat16* __restrict__ l, int n4)
{
    int i = blockIdx.x * blockDim.x + threadIdx.x;
    if (i >= n4) return;
    float4 v = ((const float4*)x)[i];
    uint32_t h0, l0, h1, l1;
    split_pack(v.x, v.y, h0, l0);
    split_pack(v.z, v.w, h1, l1);
    ((uint32_t*)h)[2*i]   = h0;
    ((uint32_t*)h)[2*i+1] = h1;
    ((uint32_t*)l)[2*i]   = l0;
    ((uint32_t*)l)[2*i+1] = l1;
}

// ---------------------------------------------------------------------------
// C[M,N] = A @ B^T via HMMA, split-bf16. If C != nullptr: fp32 output.
// Else: output written pre-split into Ch/Cl (bf16 hi/lo).
// ---------------------------------------------------------------------------
#define TSTRIDE 40

__global__ __launch_bounds__(256) void gemm_mma(
    const __nv_bfloat16* __restrict__ Ah, const __nv_bfloat16* __restrict__ Al,
    const __nv_bfloat16* __restrict__ Bh, const __nv_bfloat16* __restrict__ Bl,
    float* __restrict__ C,
    __nv_bfloat16* __restrict__ Ch, __nv_bfloat16* __restrict__ Cl,
    int M, int N, int K)
{
    __shared__ __align__(16) __nv_bfloat16 sAh[128 * TSTRIDE];
    __shared__ __align__(16) __nv_bfloat16 sAl[128 * TSTRIDE];
    __shared__ __align__(16) __nv_bfloat16 sBh[128 * TSTRIDE];
    __shared__ __align__(16) __nv_bfloat16 sBl[128 * TSTRIDE];

    const int tid  = threadIdx.x;
    const int lane = tid & 31;
    const int wid  = tid >> 5;
    const int wm   = wid & 3;
    const int wn   = wid >> 2;
    const int m0   = blockIdx.y * 128;
    const int n0   = blockIdx.x * 128;
    const int K4   = K >> 3;

    const uint4* gAh = (const uint4*)Ah;
    const uint4* gAl = (const uint4*)Al;
    const uint4* gBh = (const uint4*)Bh;
    const uint4* gBl = (const uint4*)Bl;

    const int r0 = (tid >> 2), seg = (tid & 3);

    float acc[2][8][4];
    #pragma unroll
    for (int mt = 0; mt < 2; mt++)
        #pragma unroll
        for (int nt = 0; nt < 8; nt++)
            #pragma unroll
            for (int e = 0; e < 4; e++) acc[mt][nt][e] = 0.f;

    const int rr  = lane & 7;
    const int grp = lane >> 3;
    const int aro = ((grp & 1) * 8 + rr);
    const int aco = (grp >> 1) * 8;
    const int bro = ((grp >> 1) * 8 + rr);
    const int bco = (grp & 1) * 8;

    const uint32_t bAh = smem_u32(sAh), bAl = smem_u32(sAl);
    const uint32_t bBh = smem_u32(sBh), bBl = smem_u32(sBl);

    uint4 pf[4][2];
    #pragma unroll
    for (int it = 0; it < 2; it++) {
        int r = r0 + it * 64;
        size_t oa = (size_t)(m0 + r) * K4 + seg;
        size_t ob = (size_t)(n0 + r) * K4 + seg;
        pf[0][it] = gAh[oa]; pf[1][it] = gAl[oa];
        pf[2][it] = gBh[ob]; pf[3][it] = gBl[ob];
    }

    const int nchunks = K / 32;
    for (int c = 0; c < nchunks; ++c) {
        __syncthreads();
        #pragma unroll
        for (int it = 0; it < 2; it++) {
            int r = r0 + it * 64;
            int so = r * TSTRIDE + seg * 8;
            *(uint4*)&sAh[so] = pf[0][it];
            *(uint4*)&sAl[so] = pf[1][it];
            *(uint4*)&sBh[so] = pf[2][it];
            *(uint4*)&sBl[so] = pf[3][it];
        }
        __syncthreads();

        if (c + 1 < nchunks) {
            #pragma unroll
            for (int it = 0; it < 2; it++) {
                int r = r0 + it * 64;
                size_t oa = (size_t)(m0 + r) * K4 + (size_t)(c + 1) * 4 + seg;
                size_t ob = (size_t)(n0 + r) * K4 + (size_t)(c + 1) * 4 + seg;
                pf[0][it] = gAh[oa]; pf[1][it] = gAl[oa];
                pf[2][it] = gBh[ob]; pf[3][it] = gBl[ob];
            }
        }

        #pragma unroll
        for (int ks = 0; ks < 2; ks++) {
            const int kb = ks * 16;
            uint32_t ah[2][4], al[2][4], bh[4][4], bl[4][4];
            #pragma unroll
            for (int mt = 0; mt < 2; mt++) {
                int mbase = wm * 32 + mt * 16;
                uint32_t off = (uint32_t)(((mbase + aro) * TSTRIDE + aco + kb) * 2);
                ldm_x4(ah[mt], bAh + off);
                ldm_x4(al[mt], bAl + off);
            }
            #pragma unroll
            for (int np = 0; np < 4; np++) {
                int nbase = wn * 64 + np * 16;
                uint32_t off = (uint32_t)(((nbase + bro) * TSTRIDE + bco + kb) * 2);
                ldm_x4(bh[np], bBh + off);
                ldm_x4(bl[np], bBl + off);
            }
            #pragma unroll
            for (int mt = 0; mt < 2; mt++) {
                #pragma unroll
                for (int nt = 0; nt < 8; nt++) {
                    const uint32_t* ph = &bh[nt >> 1][(nt & 1) * 2];
                    const uint32_t* pl = &bl[nt >> 1][(nt & 1) * 2];
                    mma_bf16(acc[mt][nt], ah[mt], ph);
                    mma_bf16(acc[mt][nt], ah[mt], pl);
                    mma_bf16(acc[mt][nt], al[mt], ph);
                }
            }
        }
    }

    if (C) {
        #pragma unroll
        for (int mt = 0; mt < 2; mt++) {
            int rbase = m0 + wm * 32 + mt * 16 + (lane >> 2);
            #pragma unroll
            for (int nt = 0; nt < 8; nt++) {
                int cg = n0 + wn * 64 + nt * 8 + (lane & 3) * 2;
                float2 v0 = make_float2(acc[mt][nt][0], acc[mt][nt][1]);
                float2 v1 = make_float2(acc[mt][nt][2], acc[mt][nt][3]);
                *(float2*)(C + (size_t)rbase * N + cg)       = v0;
                *(float2*)(C + (size_t)(rbase + 8) * N + cg) = v1;
            }
        }
    } else {
        #pragma unroll
        for (int mt = 0; mt < 2; mt++) {
            int rbase = m0 + wm * 32 + mt * 16 + (lane >> 2);
            #pragma unroll
            for (int nt = 0; nt < 8; nt++) {
                int cg = n0 + wn * 64 + nt * 8 + (lane & 3) * 2;
                uint32_t hh, ll;
                split_pack(acc[mt][nt][0], acc[mt][nt][1], hh, ll);
                *(uint32_t*)&Ch[(size_t)rbase * N + cg] = hh;
                *(uint32_t*)&Cl[(size_t)rbase * N + cg] = ll;
                split_pack(acc[mt][nt][2], acc[mt][nt][3], hh, ll);
                *(uint32_t*)&Ch[(size_t)(rbase + 8) * N + cg] = hh;
                *(uint32_t*)&Cl[(size_t)(rbase + 8) * N + cg] = ll;
            }
        }
    }
}

// ---------------------------------------------------------------------------
// Flash attention on HMMA, split-bf16, cp.async double-buffered K/V.
// CTA = (128-row q tile, head), 8 warps; warp w owns q rows w*16..w*16+15.
// ---------------------------------------------------------------------------
#define AST 72
// smem layout (bf16 units): Qh[128*AST], Ql[128*AST], then 2 KV buffers of
// 4 arrays (Kh,Kl,Vh,Vl), each 64*AST.
#define Q_ELEMS   (128 * AST)
#define KVA_ELEMS (64 * AST)
#define KVB_ELEMS (4 * KVA_ELEMS)
#define ATTN_SMEM ((2 * Q_ELEMS + 2 * KVB_ELEMS) * 2)

__global__ __launch_bounds__(256, 1) void attn_mma(
    const __nv_bfloat16* __restrict__ Qh, const __nv_bfloat16* __restrict__ Ql,
    const __nv_bfloat16* __restrict__ Kh, const __nv_bfloat16* __restrict__ Kl,
    const __nv_bfloat16* __restrict__ Vh, const __nv_bfloat16* __restrict__ Vl,
    __nv_bfloat16* __restrict__ Oh, __nv_bfloat16* __restrict__ Ol)
{
    extern __shared__ __align__(16) __nv_bfloat16 sm[];
    __nv_bfloat16* sQh = sm;
    __nv_bfloat16* sQl = sm + Q_ELEMS;
    __nv_bfloat16* sKV = sm + 2 * Q_ELEMS;

    const int qt = (int)gridDim.x - 1 - (int)blockIdx.x;  // longest first
    const int h  = blockIdx.y;
    const int tid = threadIdx.x, lane = tid & 31, wid = tid >> 5;
    const int rr = lane & 7, grp = lane >> 3;
    const int aro = (grp & 1) * 8 + rr, aco = (grp >> 1) * 8;
    const int bro = (grp >> 1) * 8 + rr, bco = (grp & 1) * 8;

    // ---- load Q tile (128 x 64 hi/lo) ----
    #pragma unroll
    for (int it = 0; it < 4; it++) {
        int idx = it * 256 + tid;
        int row = idx >> 3, seg = idx & 7;
        size_t go = (size_t)(qt*128 + row) * D_MODEL + h*HD + seg*8;
        *(uint4*)&sQh[row*AST + seg*8] = *(const uint4*)(Qh + go);
        *(uint4*)&sQl[row*AST + seg*8] = *(const uint4*)(Ql + go);
    }
    __syncthreads();

    uint32_t qfh[4][4], qfl[4][4];
    {
        const uint32_t bQh = smem_u32(sQh), bQl = smem_u32(sQl);
        #pragma unroll
        for (int ks = 0; ks < 4; ks++) {
            uint32_t off = (uint32_t)(((wid*16 + aro) * AST + aco + ks*16) * 2);
            ldm_x4(qfh[ks], bQh + off);
            ldm_x4(qfl[ks], bQl + off);
        }
    }

    const int nkt = 2*qt + 2;
    const uint32_t kvbase = smem_u32(sKV);

    // per-thread load coords (2 uint4 per array per tile)
    const int lrow0 = tid >> 3, lseg = tid & 7;   // rows lrow0, lrow0+32

    // issue K/V tile kt into buffer b
    auto issue_kv = [&](int kt, int b) {
        const uint32_t bb = kvbase + (uint32_t)(b * KVB_ELEMS * 2);
        #pragma unroll
        for (int p = 0; p < 2; p++) {
            int row = lrow0 + p * 32;
            size_t go = (size_t)(kt*64 + row) * D_MODEL + h*HD + lseg*8;
            uint32_t so = (uint32_t)((row*AST + lseg*8) * 2);
            CP_ASYNC16(bb + 0*KVA_ELEMS*2 + so, Kh + go);
            CP_ASYNC16(bb + 1*KVA_ELEMS*2 + so, Kl + go);
            CP_ASYNC16(bb + 2*KVA_ELEMS*2 + so, Vh + go);
            CP_ASYNC16(bb + 3*KVA_ELEMS*2 + so, Vl + go);
        }
    };

    issue_kv(0, 0);
    CP_COMMIT();
    if (nkt > 1) issue_kv(1, 1);
    CP_COMMIT();

    float m0 = -1e30f, m1 = -1e30f, l0 = 0.f, l1 = 0.f;
    float o[8][4];
    #pragma unroll
    for (int nt = 0; nt < 8; nt++)
        #pragma unroll
        for (int e = 0; e < 4; e++) o[nt][e] = 0.f;

    const int wrow0 = qt*128 + wid*16;   // first global q row of this warp

    for (int kt = 0; kt < nkt; kt++) {
        CP_WAIT1();
        __syncthreads();

        const uint32_t bb  = kvbase + (uint32_t)((kt & 1) * KVB_ELEMS * 2);
        const uint32_t bKh = bb;
        const uint32_t bKl = bb + 1*KVA_ELEMS*2;
        const uint32_t bVh = bb + 2*KVA_ELEMS*2;
        const uint32_t bVl = bb + 3*KVA_ELEMS*2;

        if (kt*64 <= wrow0 + 15) {   // tile not fully above-diagonal for warp
            // ---- QK^T ----
            float s[8][4];
            #pragma unroll
            for (int nt = 0; nt < 8; nt++)
                #pragma unroll
                for (int e = 0; e < 4; e++) s[nt][e] = 0.f;

            #pragma unroll
            for (int ks = 0; ks < 4; ks++) {
                uint32_t kfh[4][4], kfl[4][4];
                #pragma unroll
                for (int np = 0; np < 4; np++) {
                    uint32_t off = (uint32_t)(((np*16 + bro) * AST + bco + ks*16) * 2);
                    ldm_x4(kfh[np], bKh + off);
                    ldm_x4(kfl[np], bKl + off);
                }
                #pragma unroll
                for (int np = 0; np < 4; np++)
                    #pragma unroll
                    for (int hf = 0; hf < 2; hf++) {
                        int nt = np*2 + hf;
                        mma_bf16(s[nt], qfh[ks], &kfh[np][hf*2]);
                        mma_bf16(s[nt], qfh[ks], &kfl[np][hf*2]);
                        mma_bf16(s[nt], qfl[ks], &kfh[np][hf*2]);
                    }
            }

            // ---- scale + causal mask ----
            const bool needmask = (kt*64 + 63) > wrow0;
            const int r_in = (lane >> 2);
            const int cbase = 2*(lane & 3);
            #pragma unroll
            for (int nt = 0; nt < 8; nt++) {
                #pragma unroll
                for (int e = 0; e < 4; e++) {
                    float v = s[nt][e] * SCALE;
                    if (needmask) {
                        int c = kt*64 + nt*8 + cbase + (e & 1);
                        int r = wrow0 + r_in + (e >> 1) * 8;
                        if (c > r) v = -1e30f;
                    }
                    s[nt][e] = v;
                }
            }

            // ---- online softmax ----
            float mx0 = -1e30f, mx1 = -1e30f;
            #pragma unroll
            for (int nt = 0; nt < 8; nt++) {
                mx0 = fmaxf(mx0, fmaxf(s[nt][0], s[nt][1]));
                mx1 = fmaxf(mx1, fmaxf(s[nt][2], s[nt][3]));
            }
            mx0 = fmaxf(mx0, __shfl_xor_sync(0xffffffffu, mx0, 1));
            mx0 = fmaxf(mx0, __shfl_xor_sync(0xffffffffu, mx0, 2));
            mx1 = fmaxf(mx1, __shfl_xor_sync(0xffffffffu, mx1, 1));
            mx1 = fmaxf(mx1, __shfl_xor_sync(0xffffffffu, mx1, 2));

            float mn0 = fmaxf(m0, mx0), mn1 = fmaxf(m1, mx1);
            float a0 = __expf(m0 - mn0), a1 = __expf(m1 - mn1);
            float rs0 = 0.f, rs1 = 0.f;
            #pragma unroll
            for (int nt = 0; nt < 8; nt++) {
                s[nt][0] = __expf(s[nt][0] - mn0);
                s[nt][1] = __expf(s[nt][1] - mn0);
                s[nt][2] = __expf(s[nt][2] - mn1);
                s[nt][3] = __expf(s[nt][3] - mn1);
                rs0 += s[nt][0] + s[nt][1];
                rs1 += s[nt][2] + s[nt][3];
            }
            rs0 += __shfl_xor_sync(0xffffffffu, rs0, 1);
            rs0 += __shfl_xor_sync(0xffffffffu, rs0, 2);
            rs1 += __shfl_xor_sync(0xffffffffu, rs1, 1);
            rs1 += __shfl_xor_sync(0xffffffffu, rs1, 2);

            l0 = l0 * a0 + rs0;  l1 = l1 * a1 + rs1;
            m0 = mn0;            m1 = mn1;
            #pragma unroll
            for (int nt = 0; nt < 8; nt++) {
                o[nt][0] *= a0; o[nt][1] *= a0;
                o[nt][2] *= a1; o[nt][3] *= a1;
            }

            // ---- P -> A fragments (register split) ----
            uint32_t aph[4][4], apl[4][4];
            #pragma unroll
            for (int t = 0; t < 4; t++) {
                split_pack(s[2*t  ][0], s[2*t  ][1], aph[t][0], apl[t][0]);
                split_pack(s[2*t  ][2], s[2*t  ][3], aph[t][1], apl[t][1]);
                split_pack(s[2*t+1][0], s[2*t+1][1], aph[t][2], apl[t][2]);
                split_pack(s[2*t+1][2], s[2*t+1][3], aph[t][3], apl[t][3]);
            }

            // ---- O += P @ V ----
            #pragma unroll
            for (int ks = 0; ks < 4; ks++) {
                #pragma unroll
                for (int np = 0; np < 4; np++) {
                    uint32_t vfh[4], vfl[4];
                    uint32_t off = (uint32_t)(((ks*16 + (grp & 1)*8 + rr) * AST
                                               + np*16 + (grp >> 1)*8) * 2);
                    ldm_x4_t(vfh, bVh + off);
                    ldm_x4_t(vfl, bVl + off);
                    #pragma unroll
                    for (int hf = 0; hf < 2; hf++) {
                        int nt = np*2 + hf;
                        mma_bf16(o[nt], aph[ks], &vfh[hf*2]);
                        mma_bf16(o[nt], aph[ks], &vfl[hf*2]);
                        mma_bf16(o[nt], apl[ks], &vfh[hf*2]);
                    }
                }
            }
        }

        __syncthreads();
        if (kt + 2 < nkt) issue_kv(kt + 2, kt & 1);
        CP_COMMIT();
    }

    // ---- epilogue: normalize + write pre-split bf16 hi/lo ----
    float inv0 = 1.f / l0, inv1 = 1.f / l1;
    int row0 = wrow0 + (lane >> 2);
    #pragma unroll
    for (int nt = 0; nt < 8; nt++) {
        int col = h*HD + nt*8 + 2*(lane & 3);
        uint32_t hh, ll;
        split_pack(o[nt][0]*inv0, o[nt][1]*inv0, hh, ll);
        *(uint32_t*)&Oh[(size_t)row0 * D_MODEL + col] = hh;
        *(uint32_t*)&Ol[(size_t)row0 * D_MODEL + col] = ll;
        split_pack(o[nt][2]*inv1, o[nt][3]*inv1, hh, ll);
        *(uint32_t*)&Oh[(size_t)(row0+8) * D_MODEL + col] = hh;
        *(uint32_t*)&Ol[(size_t)(row0+8) * D_MODEL + col] = ll;
    }
}

// ---------------------------------------------------------------------------
extern "C" void kernel_launch(void* const* d_in, const int* in_sizes, int n_in,
                              void* d_out, int out_size)
{
    const float* x  = (const float*)d_in[0];
    const float* Wq = (const float*)d_in[1];
    const float* Wk = (const float*)d_in[2];
    const float* Wv = (const float*)d_in[3];
    const float* Wo = (const float*)d_in[4];
    float* out = (float*)d_out;

    void *pxh, *pxl, *pobh, *pobl;
    void *pqh, *pql, *pkh, *pkl, *pvh, *pvl;
    void *pwqh, *pwql, *pwkh, *pwkl, *pwvh, *pwvl, *pwoh, *pwol;
    cudaGetSymbolAddress(&pxh, g_xh); cudaGetSymbolAddress(&pxl, g_xl);
    cudaGetSymbolAddress(&pobh, g_obh); cudaGetSymbolAddress(&pobl, g_obl);
    cudaGetSymbolAddress(&pqh, g_qh); cudaGetSymbolAddress(&pql, g_ql);
    cudaGetSymbolAddress(&pkh, g_kh); cudaGetSymbolAddress(&pkl, g_kl);
    cudaGetSymbolAddress(&pvh, g_vh); cudaGetSymbolAddress(&pvl, g_vl);
    cudaGetSymbolAddress(&pwqh, g_wqh); cudaGetSymbolAddress(&pwql, g_wql);
    cudaGetSymbolAddress(&pwkh, g_wkh); cudaGetSymbolAddress(&pwkl, g_wkl);
    cudaGetSymbolAddress(&pwvh, g_wvh); cudaGetSymbolAddress(&pwvl, g_wvl);
    cudaGetSymbolAddress(&pwoh, g_woh); cudaGetSymbolAddress(&pwol, g_wol);

    cudaFuncSetAttribute(attn_mma,
                         cudaFuncAttributeMaxDynamicSharedMemorySize, ATTN_SMEM);

    const int NX4 = S_LEN * D_MODEL / 4;
    const int NW4 = D_MODEL * D_MODEL / 4;
    split_kernel<<<NX4/256, 256>>>(x,  (__nv_bfloat16*)pxh,  (__nv_bfloat16*)pxl,  NX4);
    split_kernel<<<NW4/256, 256>>>(Wq, (__nv_bfloat16*)pwqh, (__nv_bfloat16*)pwql, NW4);
    split_kernel<<<NW4/256, 256>>>(Wk, (__nv_bfloat16*)pwkh, (__nv_bfloat16*)pwkl, NW4);
    split_kernel<<<NW4/256, 256>>>(Wv, (__nv_bfloat16*)pwvh, (__nv_bfloat16*)pwvl, NW4);
    split_kernel<<<NW4/256, 256>>>(Wo, (__nv_bfloat16*)pwoh, (__nv_bfloat16*)pwol, NW4);

    dim3 gg(D_MODEL / 128, S_LEN / 128);   // (8, 32)
    gemm_mma<<<gg, 256>>>(
        (const __nv_bfloat16*)pxh, (const __nv_bfloat16*)pxl,
        (const __nv_bfloat16*)pwqh, (const __nv_bfloat16*)pwql,
        nullptr, (__nv_bfloat16*)pqh, (__nv_bfloat16*)pql,
        S_LEN, D_MODEL, D_MODEL);
    gemm_mma<<<gg, 256>>>(
        (const __nv_bfloat16*)pxh, (const __nv_bfloat16*)pxl,
        (const __nv_bfloat16*)pwkh, (const __nv_bfloat16*)pwkl,
        nullptr, (__nv_bfloat16*)pkh, (__nv_bfloat16*)pkl,
        S_LEN, D_MODEL, D_MODEL);
    gemm_mma<<<gg, 256>>>(
        (const __nv_bfloat16*)pxh, (const __nv_bfloat16*)pxl,
        (const __nv_bfloat16*)pwvh, (const __nv_bfloat16*)pwvl,
        nullptr, (__nv_bfloat16*)pvh, (__nv_bfloat16*)pvl,
        S_LEN, D_MODEL, D_MODEL);

    dim3 ga(S_LEN / 128, N_HEADS);          // (32, 16)
    attn_mma<<<ga, 256, ATTN_SMEM>>>(
        (const __nv_bfloat16*)pqh, (const __nv_bfloat16*)pql,
        (const __nv_bfloat16*)pkh, (const __nv_bfloat16*)pkl,
        (const __nv_bfloat16*)pvh, (const __nv_bfloat16*)pvl,
        (__nv_bfloat16*)pobh, (__nv_bfloat16*)pobl);

    gemm_mma<<<gg, 256>>>(
        (const __nv_bfloat16*)pobh, (const __nv_bfloat16*)pobl,
        (const __nv_bfloat16*)pwoh, (const __nv_bfloat16*)pwol,
        out, nullptr, nullptr,
        S_LEN, D_MODEL, D_MODEL);
}

// round 6
// speedup vs baseline: 2.9016x; 1.0576x over previous
#include <cuda_runtime.h>
#include <cuda_bf16.h>
#include <cstdint>

#define S_LEN   4096
#define D_MODEL 1024
#define N_HEADS 16
#define HD      64
#define SCALE   0.125f

// ---------------------------------------------------------------------------
// Scratch (device globals: allocation-free)
// ---------------------------------------------------------------------------
__device__ __align__(16) __nv_bfloat16 g_xh [S_LEN * D_MODEL];
__device__ __align__(16) __nv_bfloat16 g_xl [S_LEN * D_MODEL];
__device__ __align__(16) __nv_bfloat16 g_obh[S_LEN * D_MODEL];
__device__ __align__(16) __nv_bfloat16 g_obl[S_LEN * D_MODEL];
__device__ __align__(16) __nv_bfloat16 g_qh [S_LEN * D_MODEL];
__device__ __align__(16) __nv_bfloat16 g_ql [S_LEN * D_MODEL];
__device__ __align__(16) __nv_bfloat16 g_kh [S_LEN * D_MODEL];
__device__ __align__(16) __nv_bfloat16 g_kl [S_LEN * D_MODEL];
__device__ __align__(16) __nv_bfloat16 g_vh [S_LEN * D_MODEL];
__device__ __align__(16) __nv_bfloat16 g_vl [S_LEN * D_MODEL];
__device__ __align__(16) __nv_bfloat16 g_wqh[D_MODEL * D_MODEL];
__device__ __align__(16) __nv_bfloat16 g_wql[D_MODEL * D_MODEL];
__device__ __align__(16) __nv_bfloat16 g_wkh[D_MODEL * D_MODEL];
__device__ __align__(16) __nv_bfloat16 g_wkl[D_MODEL * D_MODEL];
__device__ __align__(16) __nv_bfloat16 g_wvh[D_MODEL * D_MODEL];
__device__ __align__(16) __nv_bfloat16 g_wvl[D_MODEL * D_MODEL];
__device__ __align__(16) __nv_bfloat16 g_woh[D_MODEL * D_MODEL];
__device__ __align__(16) __nv_bfloat16 g_wol[D_MODEL * D_MODEL];

// ---------------------------------------------------------------------------
// helpers
// ---------------------------------------------------------------------------
__device__ __forceinline__ uint32_t smem_u32(const void* p) {
    uint32_t a;
    asm("{ .reg .u64 t; cvta.to.shared.u64 t, %1; cvt.u32.u64 %0, t; }"
        : "=r"(a) : "l"(p));
    return a;
}

__device__ __forceinline__ void ldm_x4(uint32_t* r, uint32_t addr) {
    asm volatile("ldmatrix.sync.aligned.m8n8.x4.shared.b16 {%0,%1,%2,%3}, [%4];"
                 : "=r"(r[0]), "=r"(r[1]), "=r"(r[2]), "=r"(r[3]) : "r"(addr));
}
__device__ __forceinline__ void ldm_x4_t(uint32_t* r, uint32_t addr) {
    asm volatile("ldmatrix.sync.aligned.m8n8.x4.trans.shared.b16 {%0,%1,%2,%3}, [%4];"
                 : "=r"(r[0]), "=r"(r[1]), "=r"(r[2]), "=r"(r[3]) : "r"(addr));
}

__device__ __forceinline__ void mma_bf16(float* c, const uint32_t* a,
                                         const uint32_t* b) {
    asm volatile(
        "mma.sync.aligned.m16n8k16.row.col.f32.bf16.bf16.f32 "
        "{%0,%1,%2,%3}, {%4,%5,%6,%7}, {%8,%9}, {%0,%1,%2,%3};"
        : "+f"(c[0]), "+f"(c[1]), "+f"(c[2]), "+f"(c[3])
        : "r"(a[0]), "r"(a[1]), "r"(a[2]), "r"(a[3]), "r"(b[0]), "r"(b[1]));
}

__device__ __forceinline__ void split_pack(float x, float y,
                                           uint32_t& hi, uint32_t& lo) {
    __nv_bfloat16 hx = __float2bfloat16_rn(x), hy = __float2bfloat16_rn(y);
    __nv_bfloat16 lx = __float2bfloat16_rn(x - __bfloat162float(hx));
    __nv_bfloat16 ly = __float2bfloat16_rn(y - __bfloat162float(hy));
    __nv_bfloat162 hp; hp.x = hx; hp.y = hy;
    __nv_bfloat162 lp; lp.x = lx; lp.y = ly;
    hi = *(uint32_t*)&hp; lo = *(uint32_t*)&lp;
}

#define CP_ASYNC16(saddr, gptr) \
    asm volatile("cp.async.cg.shared.global [%0], [%1], 16;" :: "r"(saddr), "l"(gptr))
#define CP_COMMIT() asm volatile("cp.async.commit_group;" ::: "memory")
#define CP_WAIT1()  asm volatile("cp.async.wait_group 1;" ::: "memory")

// ---------------------------------------------------------------------------
// fp32 -> (bf16 hi, bf16 lo) split
// ---------------------------------------------------------------------------
__global__ void split_kernel(const float* __restrict__ x,
                             __nv_bfloat16* __restrict__ h,
                             __nv_bfloat16* __restrict__ l, int n4)
{
    int i = blockIdx.x * blockDim.x + threadIdx.x;
    if (i >= n4) return;
    float4 v = ((const float4*)x)[i];
    uint32_t h0, l0, h1, l1;
    split_pack(v.x, v.y, h0, l0);
    split_pack(v.z, v.w, h1, l1);
    ((uint32_t*)h)[2*i]   = h0;
    ((uint32_t*)h)[2*i+1] = h1;
    ((uint32_t*)l)[2*i]   = l0;
    ((uint32_t*)l)[2*i+1] = l1;
}

// ---------------------------------------------------------------------------
// Pipelined HMMA split-bf16 GEMM core. C[M,N] = A[M,K] @ B[N,K]^T.
// 128x128 CTA tile, BK=32, cp.async 2-stage double buffer, 8 warps (4m x 2n),
// 2 CTAs/SM. Output either fp32 (C) or pre-split bf16 (Ch/Cl).
// ---------------------------------------------------------------------------
#define TSTRIDE 40
#define ARR_B   (128 * TSTRIDE * 2)     // bytes per array per stage (10240)
#define STAGE_B (4 * ARR_B)             // Ah, Al, Bh, Bl  (40960)
#define GEMM_SMEM (2 * STAGE_B)         // 81920

struct GemmOut {
    float* C;
    __nv_bfloat16* Ch;
    __nv_bfloat16* Cl;
};

__device__ __forceinline__ void gemm_core(
    const __nv_bfloat16* __restrict__ Ah, const __nv_bfloat16* __restrict__ Al,
    const __nv_bfloat16* __restrict__ Bh, const __nv_bfloat16* __restrict__ Bl,
    GemmOut outp, int m0, int n0, int N, int K, char* smbase)
{
    const int tid  = threadIdx.x;
    const int lane = tid & 31;
    const int wid  = tid >> 5;
    const int wm   = wid & 3;
    const int wn   = wid >> 2;

    const uint32_t sb = smem_u32(smbase);

    // per-thread cp.async coords: 2 chunks per array per stage
    const int lrow = tid >> 2, lseg = tid & 3;  // rows lrow, lrow+64

    auto issue = [&](int c, int s) {
        const uint32_t b = sb + (uint32_t)(s * STAGE_B);
        #pragma unroll
        for (int p = 0; p < 2; p++) {
            int row = lrow + p * 64;
            uint32_t so = (uint32_t)((row * TSTRIDE + lseg * 8) * 2);
            size_t goA = (size_t)(m0 + row) * K + c * 32 + lseg * 8;
            size_t goB = (size_t)(n0 + row) * K + c * 32 + lseg * 8;
            CP_ASYNC16(b + 0*ARR_B + so, Ah + goA);
            CP_ASYNC16(b + 1*ARR_B + so, Al + goA);
            CP_ASYNC16(b + 2*ARR_B + so, Bh + goB);
            CP_ASYNC16(b + 3*ARR_B + so, Bl + goB);
        }
    };

    float acc[2][8][4];
    #pragma unroll
    for (int mt = 0; mt < 2; mt++)
        #pragma unroll
        for (int nt = 0; nt < 8; nt++)
            #pragma unroll
            for (int e = 0; e < 4; e++) acc[mt][nt][e] = 0.f;

    const int rr  = lane & 7;
    const int grp = lane >> 3;
    const int aro = (grp & 1) * 8 + rr;
    const int aco = (grp >> 1) * 8;
    const int bro = (grp >> 1) * 8 + rr;
    const int bco = (grp & 1) * 8;

    const int nchunks = K / 32;
    issue(0, 0); CP_COMMIT();
    issue(1, 1); CP_COMMIT();

    for (int c = 0; c < nchunks; ++c) {
        CP_WAIT1();
        __syncthreads();
        const uint32_t b   = sb + (uint32_t)((c & 1) * STAGE_B);
        const uint32_t bAh = b, bAl = b + ARR_B;
        const uint32_t bBh = b + 2*ARR_B, bBl = b + 3*ARR_B;

        #pragma unroll
        for (int ks = 0; ks < 2; ks++) {
            const int kb = ks * 16;
            uint32_t ah[2][4], al[2][4];
            #pragma unroll
            for (int mt = 0; mt < 2; mt++) {
                uint32_t off = (uint32_t)(((wm*32 + mt*16 + aro) * TSTRIDE + aco + kb) * 2);
                ldm_x4(ah[mt], bAh + off);
                ldm_x4(al[mt], bAl + off);
            }
            #pragma unroll
            for (int np = 0; np < 4; np++) {
                uint32_t bh[4], bl[4];
                uint32_t off = (uint32_t)(((wn*64 + np*16 + bro) * TSTRIDE + bco + kb) * 2);
                ldm_x4(bh, bBh + off);
                ldm_x4(bl, bBl + off);
                #pragma unroll
                for (int mt = 0; mt < 2; mt++)
                    #pragma unroll
                    for (int hf = 0; hf < 2; hf++) {
                        int nt = np*2 + hf;
                        mma_bf16(acc[mt][nt], ah[mt], &bh[hf*2]);
                        mma_bf16(acc[mt][nt], ah[mt], &bl[hf*2]);
                        mma_bf16(acc[mt][nt], al[mt], &bh[hf*2]);
                    }
            }
        }
        __syncthreads();
        if (c + 2 < nchunks) issue(c + 2, c & 1);
        CP_COMMIT();
    }

    if (outp.C) {
        #pragma unroll
        for (int mt = 0; mt < 2; mt++) {
            int rbase = m0 + wm * 32 + mt * 16 + (lane >> 2);
            #pragma unroll
            for (int nt = 0; nt < 8; nt++) {
                int cg = n0 + wn * 64 + nt * 8 + (lane & 3) * 2;
                *(float2*)(outp.C + (size_t)rbase * N + cg) =
                    make_float2(acc[mt][nt][0], acc[mt][nt][1]);
                *(float2*)(outp.C + (size_t)(rbase + 8) * N + cg) =
                    make_float2(acc[mt][nt][2], acc[mt][nt][3]);
            }
        }
    } else {
        #pragma unroll
        for (int mt = 0; mt < 2; mt++) {
            int rbase = m0 + wm * 32 + mt * 16 + (lane >> 2);
            #pragma unroll
            for (int nt = 0; nt < 8; nt++) {
                int cg = n0 + wn * 64 + nt * 8 + (lane & 3) * 2;
                uint32_t hh, ll;
                split_pack(acc[mt][nt][0], acc[mt][nt][1], hh, ll);
                *(uint32_t*)&outp.Ch[(size_t)rbase * N + cg] = hh;
                *(uint32_t*)&outp.Cl[(size_t)rbase * N + cg] = ll;
                split_pack(acc[mt][nt][2], acc[mt][nt][3], hh, ll);
                *(uint32_t*)&outp.Ch[(size_t)(rbase + 8) * N + cg] = hh;
                *(uint32_t*)&outp.Cl[(size_t)(rbase + 8) * N + cg] = ll;
            }
        }
    }
}

// Fused QKV: grid (24, 32); blockIdx.x/8 selects {Q,K,V} weight + output.
__global__ __launch_bounds__(256, 2) void gemm_qkv(
    const __nv_bfloat16* __restrict__ xh, const __nv_bfloat16* __restrict__ xl,
    const __nv_bfloat16* __restrict__ wqh, const __nv_bfloat16* __restrict__ wql,
    const __nv_bfloat16* __restrict__ wkh, const __nv_bfloat16* __restrict__ wkl,
    const __nv_bfloat16* __restrict__ wvh, const __nv_bfloat16* __restrict__ wvl,
    __nv_bfloat16* __restrict__ qh, __nv_bfloat16* __restrict__ ql,
    __nv_bfloat16* __restrict__ kh, __nv_bfloat16* __restrict__ kl,
    __nv_bfloat16* __restrict__ vh, __nv_bfloat16* __restrict__ vl)
{
    extern __shared__ char smg[];
    const int which = blockIdx.x >> 3;
    const int n0 = (blockIdx.x & 7) * 128;
    const int m0 = blockIdx.y * 128;

    const __nv_bfloat16 *Bh, *Bl;
    GemmOut o; o.C = nullptr;
    if (which == 0)      { Bh = wqh; Bl = wql; o.Ch = qh; o.Cl = ql; }
    else if (which == 1) { Bh = wkh; Bl = wkl; o.Ch = kh; o.Cl = kl; }
    else                 { Bh = wvh; Bl = wvl; o.Ch = vh; o.Cl = vl; }

    gemm_core(xh, xl, Bh, Bl, o, m0, n0, D_MODEL, D_MODEL, smg);
}

// Output projection: fp32 result.
__global__ __launch_bounds__(256, 2) void gemm_out(
    const __nv_bfloat16* __restrict__ Ah, const __nv_bfloat16* __restrict__ Al,
    const __nv_bfloat16* __restrict__ Bh, const __nv_bfloat16* __restrict__ Bl,
    float* __restrict__ C)
{
    extern __shared__ char smg[];
    GemmOut o; o.C = C; o.Ch = nullptr; o.Cl = nullptr;
    gemm_core(Ah, Al, Bh, Bl, o, blockIdx.y * 128, blockIdx.x * 128,
              D_MODEL, D_MODEL, smg);
}

// ---------------------------------------------------------------------------
// Flash attention on HMMA, split-bf16, cp.async double-buffered K/V.
// CTA = (128-row q tile, head), 8 warps; warp w owns q rows w*16..w*16+15.
// ---------------------------------------------------------------------------
#define AST 72
#define Q_ELEMS   (128 * AST)
#define KVA_ELEMS (64 * AST)
#define KVB_ELEMS (4 * KVA_ELEMS)
#define ATTN_SMEM ((2 * Q_ELEMS + 2 * KVB_ELEMS) * 2)

__global__ __launch_bounds__(256, 1) void attn_mma(
    const __nv_bfloat16* __restrict__ Qh, const __nv_bfloat16* __restrict__ Ql,
    const __nv_bfloat16* __restrict__ Kh, const __nv_bfloat16* __restrict__ Kl,
    const __nv_bfloat16* __restrict__ Vh, const __nv_bfloat16* __restrict__ Vl,
    __nv_bfloat16* __restrict__ Oh, __nv_bfloat16* __restrict__ Ol)
{
    extern __shared__ __align__(16) __nv_bfloat16 sm[];
    __nv_bfloat16* sQh = sm;
    __nv_bfloat16* sQl = sm + Q_ELEMS;
    __nv_bfloat16* sKV = sm + 2 * Q_ELEMS;

    const int qt = (int)gridDim.x - 1 - (int)blockIdx.x;
    const int h  = blockIdx.y;
    const int tid = threadIdx.x, lane = tid & 31, wid = tid >> 5;
    const int rr = lane & 7, grp = lane >> 3;
    const int aro = (grp & 1) * 8 + rr, aco = (grp >> 1) * 8;
    const int bro = (grp >> 1) * 8 + rr, bco = (grp & 1) * 8;

    #pragma unroll
    for (int it = 0; it < 4; it++) {
        int idx = it * 256 + tid;
        int row = idx >> 3, seg = idx & 7;
        size_t go = (size_t)(qt*128 + row) * D_MODEL + h*HD + seg*8;
        *(uint4*)&sQh[row*AST + seg*8] = *(const uint4*)(Qh + go);
        *(uint4*)&sQl[row*AST + seg*8] = *(const uint4*)(Ql + go);
    }
    __syncthreads();

    uint32_t qfh[4][4], qfl[4][4];
    {
        const uint32_t bQh = smem_u32(sQh), bQl = smem_u32(sQl);
        #pragma unroll
        for (int ks = 0; ks < 4; ks++) {
            uint32_t off = (uint32_t)(((wid*16 + aro) * AST + aco + ks*16) * 2);
            ldm_x4(qfh[ks], bQh + off);
            ldm_x4(qfl[ks], bQl + off);
        }
    }

    const int nkt = 2*qt + 2;
    const uint32_t kvbase = smem_u32(sKV);
    const int lrow0 = tid >> 3, lseg = tid & 7;

    auto issue_kv = [&](int kt, int b) {
        const uint32_t bb = kvbase + (uint32_t)(b * KVB_ELEMS * 2);
        #pragma unroll
        for (int p = 0; p < 2; p++) {
            int row = lrow0 + p * 32;
            size_t go = (size_t)(kt*64 + row) * D_MODEL + h*HD + lseg*8;
            uint32_t so = (uint32_t)((row*AST + lseg*8) * 2);
            CP_ASYNC16(bb + 0*KVA_ELEMS*2 + so, Kh + go);
            CP_ASYNC16(bb + 1*KVA_ELEMS*2 + so, Kl + go);
            CP_ASYNC16(bb + 2*KVA_ELEMS*2 + so, Vh + go);
            CP_ASYNC16(bb + 3*KVA_ELEMS*2 + so, Vl + go);
        }
    };

    issue_kv(0, 0);
    CP_COMMIT();
    if (nkt > 1) issue_kv(1, 1);
    CP_COMMIT();

    float m0 = -1e30f, m1 = -1e30f, l0 = 0.f, l1 = 0.f;
    float o[8][4];
    #pragma unroll
    for (int nt = 0; nt < 8; nt++)
        #pragma unroll
        for (int e = 0; e < 4; e++) o[nt][e] = 0.f;

    const int wrow0 = qt*128 + wid*16;

    for (int kt = 0; kt < nkt; kt++) {
        CP_WAIT1();
        __syncthreads();

        const uint32_t bb  = kvbase + (uint32_t)((kt & 1) * KVB_ELEMS * 2);
        const uint32_t bKh = bb;
        const uint32_t bKl = bb + 1*KVA_ELEMS*2;
        const uint32_t bVh = bb + 2*KVA_ELEMS*2;
        const uint32_t bVl = bb + 3*KVA_ELEMS*2;

        if (kt*64 <= wrow0 + 15) {
            float s[8][4];
            #pragma unroll
            for (int nt = 0; nt < 8; nt++)
                #pragma unroll
                for (int e = 0; e < 4; e++) s[nt][e] = 0.f;

            #pragma unroll
            for (int ks = 0; ks < 4; ks++) {
                uint32_t kfh[4][4], kfl[4][4];
                #pragma unroll
                for (int np = 0; np < 4; np++) {
                    uint32_t off = (uint32_t)(((np*16 + bro) * AST + bco + ks*16) * 2);
                    ldm_x4(kfh[np], bKh + off);
                    ldm_x4(kfl[np], bKl + off);
                }
                #pragma unroll
                for (int np = 0; np < 4; np++)
                    #pragma unroll
                    for (int hf = 0; hf < 2; hf++) {
                        int nt = np*2 + hf;
                        mma_bf16(s[nt], qfh[ks], &kfh[np][hf*2]);
                        mma_bf16(s[nt], qfh[ks], &kfl[np][hf*2]);
                        mma_bf16(s[nt], qfl[ks], &kfh[np][hf*2]);
                    }
            }

            const bool needmask = (kt*64 + 63) > wrow0;
            const int r_in = (lane >> 2);
            const int cbase = 2*(lane & 3);
            #pragma unroll
            for (int nt = 0; nt < 8; nt++) {
                #pragma unroll
                for (int e = 0; e < 4; e++) {
                    float v = s[nt][e] * SCALE;
                    if (needmask) {
                        int c = kt*64 + nt*8 + cbase + (e & 1);
                        int r = wrow0 + r_in + (e >> 1) * 8;
                        if (c > r) v = -1e30f;
                    }
                    s[nt][e] = v;
                }
            }

            float mx0 = -1e30f, mx1 = -1e30f;
            #pragma unroll
            for (int nt = 0; nt < 8; nt++) {
                mx0 = fmaxf(mx0, fmaxf(s[nt][0], s[nt][1]));
                mx1 = fmaxf(mx1, fmaxf(s[nt][2], s[nt][3]));
            }
            mx0 = fmaxf(mx0, __shfl_xor_sync(0xffffffffu, mx0, 1));
            mx0 = fmaxf(mx0, __shfl_xor_sync(0xffffffffu, mx0, 2));
            mx1 = fmaxf(mx1, __shfl_xor_sync(0xffffffffu, mx1, 1));
            mx1 = fmaxf(mx1, __shfl_xor_sync(0xffffffffu, mx1, 2));

            float mn0 = fmaxf(m0, mx0), mn1 = fmaxf(m1, mx1);
            float a0 = __expf(m0 - mn0), a1 = __expf(m1 - mn1);
            float rs0 = 0.f, rs1 = 0.f;
            #pragma unroll
            for (int nt = 0; nt < 8; nt++) {
                s[nt][0] = __expf(s[nt][0] - mn0);
                s[nt][1] = __expf(s[nt][1] - mn0);
                s[nt][2] = __expf(s[nt][2] - mn1);
                s[nt][3] = __expf(s[nt][3] - mn1);
                rs0 += s[nt][0] + s[nt][1];
                rs1 += s[nt][2] + s[nt][3];
            }
            rs0 += __shfl_xor_sync(0xffffffffu, rs0, 1);
            rs0 += __shfl_xor_sync(0xffffffffu, rs0, 2);
            rs1 += __shfl_xor_sync(0xffffffffu, rs1, 1);
            rs1 += __shfl_xor_sync(0xffffffffu, rs1, 2);

            l0 = l0 * a0 + rs0;  l1 = l1 * a1 + rs1;
            m0 = mn0;            m1 = mn1;
            #pragma unroll
            for (int nt = 0; nt < 8; nt++) {
                o[nt][0] *= a0; o[nt][1] *= a0;
                o[nt][2] *= a1; o[nt][3] *= a1;
            }

            uint32_t aph[4][4], apl[4][4];
            #pragma unroll
            for (int t = 0; t < 4; t++) {
                split_pack(s[2*t  ][0], s[2*t  ][1], aph[t][0], apl[t][0]);
                split_pack(s[2*t  ][2], s[2*t  ][3], aph[t][1], apl[t][1]);
                split_pack(s[2*t+1][0], s[2*t+1][1], aph[t][2], apl[t][2]);
                split_pack(s[2*t+1][2], s[2*t+1][3], aph[t][3], apl[t][3]);
            }

            #pragma unroll
            for (int ks = 0; ks < 4; ks++) {
                #pragma unroll
                for (int np = 0; np < 4; np++) {
                    uint32_t vfh[4], vfl[4];
                    uint32_t off = (uint32_t)(((ks*16 + (grp & 1)*8 + rr) * AST
                                               + np*16 + (grp >> 1)*8) * 2);
                    ldm_x4_t(vfh, bVh + off);
                    ldm_x4_t(vfl, bVl + off);
                    #pragma unroll
                    for (int hf = 0; hf < 2; hf++) {
                        int nt = np*2 + hf;
                        mma_bf16(o[nt], aph[ks], &vfh[hf*2]);
                        mma_bf16(o[nt], aph[ks], &vfl[hf*2]);
                        mma_bf16(o[nt], apl[ks], &vfh[hf*2]);
                    }
                }
            }
        }

        __syncthreads();
        if (kt + 2 < nkt) issue_kv(kt + 2, kt & 1);
        CP_COMMIT();
    }

    float inv0 = 1.f / l0, inv1 = 1.f / l1;
    int row0 = wrow0 + (lane >> 2);
    #pragma unroll
    for (int nt = 0; nt < 8; nt++) {
        int col = h*HD + nt*8 + 2*(lane & 3);
        uint32_t hh, ll;
        split_pack(o[nt][0]*inv0, o[nt][1]*inv0, hh, ll);
        *(uint32_t*)&Oh[(size_t)row0 * D_MODEL + col] = hh;
        *(uint32_t*)&Ol[(size_t)row0 * D_MODEL + col] = ll;
        split_pack(o[nt][2]*inv1, o[nt][3]*inv1, hh, ll);
        *(uint32_t*)&Oh[(size_t)(row0+8) * D_MODEL + col] = hh;
        *(uint32_t*)&Ol[(size_t)(row0+8) * D_MODEL + col] = ll;
    }
}

// ---------------------------------------------------------------------------
extern "C" void kernel_launch(void* const* d_in, const int* in_sizes, int n_in,
                              void* d_out, int out_size)
{
    const float* x  = (const float*)d_in[0];
    const float* Wq = (const float*)d_in[1];
    const float* Wk = (const float*)d_in[2];
    const float* Wv = (const float*)d_in[3];
    const float* Wo = (const float*)d_in[4];
    float* out = (float*)d_out;

    void *pxh, *pxl, *pobh, *pobl;
    void *pqh, *pql, *pkh, *pkl, *pvh, *pvl;
    void *pwqh, *pwql, *pwkh, *pwkl, *pwvh, *pwvl, *pwoh, *pwol;
    cudaGetSymbolAddress(&pxh, g_xh); cudaGetSymbolAddress(&pxl, g_xl);
    cudaGetSymbolAddress(&pobh, g_obh); cudaGetSymbolAddress(&pobl, g_obl);
    cudaGetSymbolAddress(&pqh, g_qh); cudaGetSymbolAddress(&pql, g_ql);
    cudaGetSymbolAddress(&pkh, g_kh); cudaGetSymbolAddress(&pkl, g_kl);
    cudaGetSymbolAddress(&pvh, g_vh); cudaGetSymbolAddress(&pvl, g_vl);
    cudaGetSymbolAddress(&pwqh, g_wqh); cudaGetSymbolAddress(&pwql, g_wql);
    cudaGetSymbolAddress(&pwkh, g_wkh); cudaGetSymbolAddress(&pwkl, g_wkl);
    cudaGetSymbolAddress(&pwvh, g_wvh); cudaGetSymbolAddress(&pwvl, g_wvl);
    cudaGetSymbolAddress(&pwoh, g_woh); cudaGetSymbolAddress(&pwol, g_wol);

    cudaFuncSetAttribute(attn_mma,
                         cudaFuncAttributeMaxDynamicSharedMemorySize, ATTN_SMEM);
    cudaFuncSetAttribute(gemm_qkv,
                         cudaFuncAttributeMaxDynamicSharedMemorySize, GEMM_SMEM);
    cudaFuncSetAttribute(gemm_out,
                         cudaFuncAttributeMaxDynamicSharedMemorySize, GEMM_SMEM);

    const int NX4 = S_LEN * D_MODEL / 4;
    const int NW4 = D_MODEL * D_MODEL / 4;
    split_kernel<<<NX4/256, 256>>>(x,  (__nv_bfloat16*)pxh,  (__nv_bfloat16*)pxl,  NX4);
    split_kernel<<<NW4/256, 256>>>(Wq, (__nv_bfloat16*)pwqh, (__nv_bfloat16*)pwql, NW4);
    split_kernel<<<NW4/256, 256>>>(Wk, (__nv_bfloat16*)pwkh, (__nv_bfloat16*)pwkl, NW4);
    split_kernel<<<NW4/256, 256>>>(Wv, (__nv_bfloat16*)pwvh, (__nv_bfloat16*)pwvl, NW4);
    split_kernel<<<NW4/256, 256>>>(Wo, (__nv_bfloat16*)pwoh, (__nv_bfloat16*)pwol, NW4);

    dim3 gq(24, S_LEN / 128);   // fused QKV: 768 CTAs
    gemm_qkv<<<gq, 256, GEMM_SMEM>>>(
        (const __nv_bfloat16*)pxh, (const __nv_bfloat16*)pxl,
        (const __nv_bfloat16*)pwqh, (const __nv_bfloat16*)pwql,
        (const __nv_bfloat16*)pwkh, (const __nv_bfloat16*)pwkl,
        (const __nv_bfloat16*)pwvh, (const __nv_bfloat16*)pwvl,
        (__nv_bfloat16*)pqh, (__nv_bfloat16*)pql,
        (__nv_bfloat16*)pkh, (__nv_bfloat16*)pkl,
        (__nv_bfloat16*)pvh, (__nv_bfloat16*)pvl);

    dim3 ga(S_LEN / 128, N_HEADS);
    attn_mma<<<ga, 256, ATTN_SMEM>>>(
        (const __nv_bfloat16*)pqh, (const __nv_bfloat16*)pql,
        (const __nv_bfloat16*)pkh, (const __nv_bfloat16*)pkl,
        (const __nv_bfloat16*)pvh, (const __nv_bfloat16*)pvl,
        (__nv_bfloat16*)pobh, (__nv_bfloat16*)pobl);

    dim3 go(D_MODEL / 128, S_LEN / 128);
    gemm_out<<<go, 256, GEMM_SMEM>>>(
        (const __nv_bfloat16*)pobh, (const __nv_bfloat16*)pobl,
        (const __nv_bfloat16*)pwoh, (const __nv_bfloat16*)pwol,
        out);
}